// round 1
// baseline (speedup 1.0000x reference)
#include <cuda_runtime.h>
#include <cuda_bf16.h>
#include <math.h>

// Problem dims
#define BB 4
#define SS 2048
#define DD 1024
#define HH 16
#define DK 64
#define MTOT (BB*SS)          // 8192

// Scratch (allocation-free rule: __device__ globals)
__device__ float g_Q[BB*HH*SS*DK];   // [b,h,s,dk]
__device__ float g_K[BB*HH*SS*DK];
__device__ float g_V[BB*HH*SS*DK];
__device__ float g_C[MTOT*DD];       // concat context [b*s, d]

// ---------------------------------------------------------------------------
// SGEMM 128x128x16, 256 threads, 8x8 per thread, Y = A(MxK) * W(NxK)^T + bias
// ---------------------------------------------------------------------------

// QKV projection: grid (N/128=8, M/128=64, 3); z selects q/k/v.
// Epilogue stores permuted into [b,h,s,dk] with h = n%16, dk = n/16.
__global__ __launch_bounds__(256) void qkv_kernel(
    const float* __restrict__ xq, const float* __restrict__ xk, const float* __restrict__ xv,
    const float* __restrict__ wq, const float* __restrict__ wk, const float* __restrict__ wv,
    const float* __restrict__ bq, const float* __restrict__ bk, const float* __restrict__ bv)
{
    const float *A, *W, *bias;
    float* dst;
    if (blockIdx.z == 0)      { A = xq; W = wq; bias = bq; dst = g_Q; }
    else if (blockIdx.z == 1) { A = xk; W = wk; bias = bk; dst = g_K; }
    else                      { A = xv; W = wv; bias = bv; dst = g_V; }

    __shared__ float As[16][128];
    __shared__ float Bs[16][128];

    const int tid = threadIdx.x;
    const int ty = tid >> 4;          // 0..15
    const int tx = tid & 15;          // 0..15
    const int mBase = blockIdx.y * 128;
    const int nBase = blockIdx.x * 128;

    float acc[8][8];
    #pragma unroll
    for (int i = 0; i < 8; i++)
        #pragma unroll
        for (int j = 0; j < 8; j++) acc[i][j] = 0.f;

    for (int k0 = 0; k0 < DD; k0 += 16) {
        #pragma unroll
        for (int p = 0; p < 2; p++) {
            int f = tid + p * 256;            // 0..511
            int row = f >> 2;                 // 0..127
            int kq  = (f & 3) << 2;           // 0,4,8,12
            float4 a4 = *(const float4*)(A + (size_t)(mBase + row) * DD + k0 + kq);
            As[kq + 0][row] = a4.x; As[kq + 1][row] = a4.y;
            As[kq + 2][row] = a4.z; As[kq + 3][row] = a4.w;
            float4 b4 = *(const float4*)(W + (size_t)(nBase + row) * DD + k0 + kq);
            Bs[kq + 0][row] = b4.x; Bs[kq + 1][row] = b4.y;
            Bs[kq + 2][row] = b4.z; Bs[kq + 3][row] = b4.w;
        }
        __syncthreads();
        #pragma unroll
        for (int kk = 0; kk < 16; kk++) {
            float4 a0 = *(const float4*)&As[kk][ty * 8];
            float4 a1 = *(const float4*)&As[kk][ty * 8 + 4];
            float4 b0 = *(const float4*)&Bs[kk][tx * 8];
            float4 b1 = *(const float4*)&Bs[kk][tx * 8 + 4];
            float af[8] = {a0.x, a0.y, a0.z, a0.w, a1.x, a1.y, a1.z, a1.w};
            float bf[8] = {b0.x, b0.y, b0.z, b0.w, b1.x, b1.y, b1.z, b1.w};
            #pragma unroll
            for (int i = 0; i < 8; i++)
                #pragma unroll
                for (int j = 0; j < 8; j++)
                    acc[i][j] = fmaf(af[i], bf[j], acc[i][j]);
        }
        __syncthreads();
    }

    // Epilogue: permuted store into [b, h, s, dk]
    #pragma unroll
    for (int i = 0; i < 8; i++) {
        int m = mBase + ty * 8 + i;
        int b = m >> 11;            // /2048
        int s = m & 2047;
        #pragma unroll
        for (int j = 0; j < 8; j++) {
            int n = nBase + tx * 8 + j;
            int h  = n & 15;
            int dk = n >> 4;
            float v = acc[i][j] + bias[n];
            dst[((((size_t)b * HH) + h) * SS + s) * DK + dk] = v;
        }
    }
}

// Output projection: out = g_C (MxD) @ w_o^T + b_o, plain row-major store.
__global__ __launch_bounds__(256) void oproj_kernel(
    const float* __restrict__ wo, const float* __restrict__ bo,
    float* __restrict__ out)
{
    const float* A = g_C;

    __shared__ float As[16][128];
    __shared__ float Bs[16][128];

    const int tid = threadIdx.x;
    const int ty = tid >> 4;
    const int tx = tid & 15;
    const int mBase = blockIdx.y * 128;
    const int nBase = blockIdx.x * 128;

    float acc[8][8];
    #pragma unroll
    for (int i = 0; i < 8; i++)
        #pragma unroll
        for (int j = 0; j < 8; j++) acc[i][j] = 0.f;

    for (int k0 = 0; k0 < DD; k0 += 16) {
        #pragma unroll
        for (int p = 0; p < 2; p++) {
            int f = tid + p * 256;
            int row = f >> 2;
            int kq  = (f & 3) << 2;
            float4 a4 = *(const float4*)(A + (size_t)(mBase + row) * DD + k0 + kq);
            As[kq + 0][row] = a4.x; As[kq + 1][row] = a4.y;
            As[kq + 2][row] = a4.z; As[kq + 3][row] = a4.w;
            float4 b4 = *(const float4*)(wo + (size_t)(nBase + row) * DD + k0 + kq);
            Bs[kq + 0][row] = b4.x; Bs[kq + 1][row] = b4.y;
            Bs[kq + 2][row] = b4.z; Bs[kq + 3][row] = b4.w;
        }
        __syncthreads();
        #pragma unroll
        for (int kk = 0; kk < 16; kk++) {
            float4 a0 = *(const float4*)&As[kk][ty * 8];
            float4 a1 = *(const float4*)&As[kk][ty * 8 + 4];
            float4 b0 = *(const float4*)&Bs[kk][tx * 8];
            float4 b1 = *(const float4*)&Bs[kk][tx * 8 + 4];
            float af[8] = {a0.x, a0.y, a0.z, a0.w, a1.x, a1.y, a1.z, a1.w};
            float bf[8] = {b0.x, b0.y, b0.z, b0.w, b1.x, b1.y, b1.z, b1.w};
            #pragma unroll
            for (int i = 0; i < 8; i++)
                #pragma unroll
                for (int j = 0; j < 8; j++)
                    acc[i][j] = fmaf(af[i], bf[j], acc[i][j]);
        }
        __syncthreads();
    }

    #pragma unroll
    for (int i = 0; i < 8; i++) {
        int m = mBase + ty * 8 + i;
        #pragma unroll
        for (int j = 0; j < 8; j++) {
            int n = nBase + tx * 8 + j;
            out[(size_t)m * DD + n] = acc[i][j] + bo[n];
        }
    }
}

// ---------------------------------------------------------------------------
// Causal flash attention: one block per (q-tile of 64, b*h). 256 threads.
// 4x4 per thread of the 64x64 score/output tiles. fp32 throughout.
// smem: Qs[64][64], Ks[64][65], Vs[64][65], Ps[64][64] -> 66048 bytes (dynamic)
// ---------------------------------------------------------------------------
#define ATT_SMEM_FLOATS (64*64 + 64*65 + 64*65 + 64*64)

__global__ __launch_bounds__(256) void attn_kernel()
{
    extern __shared__ float sm[];
    float* Qs = sm;                    // stride 64
    float* Ks = Qs + 64 * 64;          // stride 65
    float* Vs = Ks + 64 * 65;          // stride 65
    float* Ps = Vs + 64 * 65;          // stride 64

    const int bh = blockIdx.y;                       // b*16 + h
    const int qt = blockIdx.x;                       // query tile
    const float* Qb = g_Q + (size_t)bh * SS * DK;
    const float* Kb = g_K + (size_t)bh * SS * DK;
    const float* Vb = g_V + (size_t)bh * SS * DK;

    const int tid = threadIdx.x;
    const int ty = tid >> 4;
    const int tx = tid & 15;
    const int r0 = ty * 4;     // q rows owned
    const int c0 = tx * 4;     // cols owned

    // Load Q tile (coalesced)
    for (int e = tid; e < 64 * 64; e += 256) {
        int r = e >> 6, c = e & 63;
        Qs[r * 64 + c] = Qb[(size_t)(qt * 64 + r) * DK + c];
    }

    float mi[4], li[4], O[4][4];
    #pragma unroll
    for (int i = 0; i < 4; i++) {
        mi[i] = -INFINITY; li[i] = 0.f;
        #pragma unroll
        for (int j = 0; j < 4; j++) O[i][j] = 0.f;
    }

    const float scale = 0.125f;   // 1/sqrt(64)

    for (int kt = 0; kt <= qt; kt++) {
        __syncthreads();   // previous iter's Ps/Vs consumed; Qs visible on iter 0
        for (int e = tid; e < 64 * 64; e += 256) {
            int r = e >> 6, c = e & 63;
            Ks[r * 65 + c] = Kb[(size_t)(kt * 64 + r) * DK + c];
            Vs[r * 65 + c] = Vb[(size_t)(kt * 64 + r) * DK + c];
        }
        __syncthreads();

        // S = Q @ K^T (4x4 per thread)
        float sc[4][4];
        #pragma unroll
        for (int i = 0; i < 4; i++)
            #pragma unroll
            for (int j = 0; j < 4; j++) sc[i][j] = 0.f;

        #pragma unroll 8
        for (int kk = 0; kk < 64; kk++) {
            float qv[4], kv[4];
            #pragma unroll
            for (int i = 0; i < 4; i++) qv[i] = Qs[(r0 + i) * 64 + kk];
            #pragma unroll
            for (int j = 0; j < 4; j++) kv[j] = Ks[(c0 + j) * 65 + kk];
            #pragma unroll
            for (int i = 0; i < 4; i++)
                #pragma unroll
                for (int j = 0; j < 4; j++)
                    sc[i][j] = fmaf(qv[i], kv[j], sc[i][j]);
        }

        // scale + causal mask
        const bool diag = (kt == qt);
        #pragma unroll
        for (int i = 0; i < 4; i++) {
            int qg = qt * 64 + r0 + i;
            #pragma unroll
            for (int j = 0; j < 4; j++) {
                int kg = kt * 64 + c0 + j;
                float v = sc[i][j] * scale;
                if (diag && kg > qg) v = -INFINITY;
                sc[i][j] = v;
            }
        }

        // online softmax (row reductions across the 16-lane tx group)
        #pragma unroll
        for (int i = 0; i < 4; i++) {
            float rm = sc[i][0];
            #pragma unroll
            for (int j = 1; j < 4; j++) rm = fmaxf(rm, sc[i][j]);
            #pragma unroll
            for (int o = 8; o > 0; o >>= 1)
                rm = fmaxf(rm, __shfl_xor_sync(0xffffffffu, rm, o, 16));
            float mn = fmaxf(mi[i], rm);
            float alpha = __expf(mi[i] - mn);
            float rs = 0.f;
            #pragma unroll
            for (int j = 0; j < 4; j++) {
                float p = __expf(sc[i][j] - mn);
                sc[i][j] = p;
                rs += p;
            }
            #pragma unroll
            for (int o = 8; o > 0; o >>= 1)
                rs += __shfl_xor_sync(0xffffffffu, rs, o, 16);
            li[i] = li[i] * alpha + rs;
            mi[i] = mn;
            #pragma unroll
            for (int j = 0; j < 4; j++) O[i][j] *= alpha;
        }

        // stage P
        #pragma unroll
        for (int i = 0; i < 4; i++)
            #pragma unroll
            for (int j = 0; j < 4; j++)
                Ps[(r0 + i) * 64 + (c0 + j)] = sc[i][j];
        __syncthreads();

        // O += P @ V
        #pragma unroll 8
        for (int kk = 0; kk < 64; kk++) {
            float pv[4], vv[4];
            #pragma unroll
            for (int i = 0; i < 4; i++) pv[i] = Ps[(r0 + i) * 64 + kk];
            #pragma unroll
            for (int j = 0; j < 4; j++) vv[j] = Vs[kk * 65 + (c0 + j)];
            #pragma unroll
            for (int i = 0; i < 4; i++)
                #pragma unroll
                for (int j = 0; j < 4; j++)
                    O[i][j] = fmaf(pv[i], vv[j], O[i][j]);
        }
    }

    // concat epilogue: ctx[b, s, h*64 + dk]
    const int b = bh >> 4;
    const int h = bh & 15;
    #pragma unroll
    for (int i = 0; i < 4; i++) {
        int qg = qt * 64 + r0 + i;
        float inv = 1.0f / li[i];
        #pragma unroll
        for (int j = 0; j < 4; j++) {
            g_C[((size_t)b * SS + qg) * DD + h * DK + (c0 + j)] = O[i][j] * inv;
        }
    }
}

// ---------------------------------------------------------------------------
extern "C" void kernel_launch(void* const* d_in, const int* in_sizes, int n_in,
                              void* d_out, int out_size)
{
    const float* q   = (const float*)d_in[0];
    const float* k   = (const float*)d_in[1];
    const float* v   = (const float*)d_in[2];
    // d_in[3] = mask: provably causal tril; handled in-kernel
    const float* w_q = (const float*)d_in[4];
    const float* b_q = (const float*)d_in[5];
    const float* w_k = (const float*)d_in[6];
    const float* b_k = (const float*)d_in[7];
    const float* w_v = (const float*)d_in[8];
    const float* b_v = (const float*)d_in[9];
    const float* w_o = (const float*)d_in[10];
    const float* b_o = (const float*)d_in[11];
    float* out = (float*)d_out;

    // 1) QKV projections (fused grid.z)
    dim3 g1(DD / 128, MTOT / 128, 3);
    qkv_kernel<<<g1, 256>>>(q, k, v, w_q, w_k, w_v, b_q, b_k, b_v);

    // 2) causal flash attention
    size_t smem = (size_t)ATT_SMEM_FLOATS * sizeof(float);   // 66048 B
    cudaFuncSetAttribute(attn_kernel,
                         cudaFuncAttributeMaxDynamicSharedMemorySize, (int)smem);
    attn_kernel<<<dim3(SS / 64, BB * HH), 256, smem>>>();

    // 3) output projection
    oproj_kernel<<<dim3(DD / 128, MTOT / 128), 256>>>(w_o, b_o, out);
}

// round 3
// speedup vs baseline: 1.5997x; 1.5997x over previous
#include <cuda_runtime.h>
#include <cuda_bf16.h>
#include <math.h>
#include <stdint.h>

// Problem dims
#define BB 4
#define SS 2048
#define DD 1024
#define HH 16
#define DK 64
#define MTOT (BB*SS)          // 8192

constexpr size_t MKc = (size_t)MTOT * DD;   // 8388608
constexpr size_t KNc = (size_t)DD * DD;     // 1048576

// ---------------- scratch (__device__ globals; no allocs allowed) ----------
__device__ float g_Q[(size_t)BB*HH*SS*DK];   // [b,h,s,dk]
__device__ float g_K[(size_t)BB*HH*SS*DK];
__device__ float g_V[(size_t)BB*HH*SS*DK];
__device__ float g_C[MKc];                   // concat context [b*s, d]

// bf16 hi/lo splits
__device__ __nv_bfloat16 g_ahi[3*MKc];       // q,k,v inputs
__device__ __nv_bfloat16 g_alo[3*MKc];
__device__ __nv_bfloat16 g_whi[4*KNc];       // wq,wk,wv,wo
__device__ __nv_bfloat16 g_wlo[4*KNc];
__device__ __nv_bfloat16 g_chi[MKc];         // context split
__device__ __nv_bfloat16 g_clo[MKc];

// ---------------- PTX helpers ---------------------------------------------
__device__ __forceinline__ uint32_t smem_u32(const void* p) {
    uint32_t a;
    asm("{ .reg .u64 t; cvta.to.shared.u64 t, %1; cvt.u32.u64 %0, t; }"
        : "=r"(a) : "l"(p));
    return a;
}

__device__ __forceinline__ void cp16(uint32_t s, const void* g) {
    asm volatile("cp.async.cg.shared.global [%0], [%1], 16;" :: "r"(s), "l"(g));
}
#define CP_COMMIT() asm volatile("cp.async.commit_group;" ::: "memory")
#define CP_WAIT(n)  asm volatile("cp.async.wait_group %0;" :: "n"(n) : "memory")

__device__ __forceinline__ void ldsm4(uint32_t* r, uint32_t addr) {
    asm volatile("ldmatrix.sync.aligned.m8n8.x4.shared.b16 {%0,%1,%2,%3}, [%4];"
                 : "=r"(r[0]), "=r"(r[1]), "=r"(r[2]), "=r"(r[3]) : "r"(addr));
}
__device__ __forceinline__ void ldsm2(uint32_t* r, uint32_t addr) {
    asm volatile("ldmatrix.sync.aligned.m8n8.x2.shared.b16 {%0,%1}, [%2];"
                 : "=r"(r[0]), "=r"(r[1]) : "r"(addr));
}
__device__ __forceinline__ void mma16816(float* c, const uint32_t* a, const uint32_t* b) {
    asm volatile("mma.sync.aligned.m16n8k16.row.col.f32.bf16.bf16.f32 "
                 "{%0,%1,%2,%3}, {%4,%5,%6,%7}, {%8,%9}, {%0,%1,%2,%3};"
                 : "+f"(c[0]), "+f"(c[1]), "+f"(c[2]), "+f"(c[3])
                 : "r"(a[0]), "r"(a[1]), "r"(a[2]), "r"(a[3]),
                   "r"(b[0]), "r"(b[1]));
}

// 8-row-period XOR swizzle over 16B units within a 64B row: conflict-free LDSM
__device__ __forceinline__ uint32_t swz(int row, int u) {
    return (uint32_t)(row * 64 + ((u ^ ((row >> 1) & 3)) << 4));
}

// ---------------------------------------------------------------------------
// split kernel: fp32 -> bf16 hi + bf16 lo.  which: 0=inputs, 1=weights, 2=g_C
// ---------------------------------------------------------------------------
__global__ __launch_bounds__(256) void split_kernel(const float* __restrict__ src,
                                                    int which, size_t off, int n4)
{
    int i = blockIdx.x * blockDim.x + threadIdx.x;
    if (i >= n4) return;
    __nv_bfloat16 *hi, *lo;
    if (which == 0)      { hi = g_ahi + off; lo = g_alo + off; }
    else if (which == 1) { hi = g_whi + off; lo = g_wlo + off; }
    else                 { hi = g_chi;       lo = g_clo;       src = g_C; }
    float4 x = ((const float4*)src)[i];
    float v0 = x.x, v1 = x.y, v2 = x.z, v3 = x.w;
    __nv_bfloat16 h0 = __float2bfloat16(v0), h1 = __float2bfloat16(v1);
    __nv_bfloat16 h2 = __float2bfloat16(v2), h3 = __float2bfloat16(v3);
    __nv_bfloat16 l0 = __float2bfloat16(v0 - __bfloat162float(h0));
    __nv_bfloat16 l1 = __float2bfloat16(v1 - __bfloat162float(h1));
    __nv_bfloat16 l2 = __float2bfloat16(v2 - __bfloat162float(h2));
    __nv_bfloat16 l3 = __float2bfloat16(v3 - __bfloat162float(h3));
    ((__nv_bfloat162*)hi)[2*i + 0] = __halves2bfloat162(h0, h1);
    ((__nv_bfloat162*)hi)[2*i + 1] = __halves2bfloat162(h2, h3);
    ((__nv_bfloat162*)lo)[2*i + 0] = __halves2bfloat162(l0, l1);
    ((__nv_bfloat162*)lo)[2*i + 1] = __halves2bfloat162(l2, l3);
}

// ---------------------------------------------------------------------------
// HMMA bf16x3 GEMM: Y = A(Mx1024) @ W(Nx1024)^T + bias
// CTA tile 128x64, BK=32, 8 warps (4M x 2N), warp tile 32x32.
// Double-buffered cp.async pipeline. 3 passes: Ahi*Bhi + Ahi*Blo + Alo*Bhi.
// ---------------------------------------------------------------------------
#define BM 128
#define BN 64
#define BK 32
#define NCHUNK (DD / BK)     // 32
#define OFF_AHI 0
#define OFF_ALO 8192
#define OFF_BHI 16384
#define OFF_BLO 20480
#define STAGE   24576

__global__ __launch_bounds__(256, 2)
void hmma_gemm_kernel(int asel, int bsel, int dsel,
                      const float* __restrict__ bias, float* __restrict__ outp)
{
    __shared__ char smem[2 * STAGE];     // 48KB

    const int tid = threadIdx.x;
    const int wid = tid >> 5;
    const int lane = tid & 31;
    const int warpM = wid & 3;          // 0..3, 32 rows each
    const int warpN = wid >> 2;         // 0..1, 32 cols each
    const int mBase = blockIdx.y * BM;
    const int nBase = blockIdx.x * BN;

    const __nv_bfloat16 *Ahi, *Alo;
    if (asel < 3) { Ahi = g_ahi + (size_t)asel * MKc; Alo = g_alo + (size_t)asel * MKc; }
    else          { Ahi = g_chi; Alo = g_clo; }
    const __nv_bfloat16* Bhi = g_whi + (size_t)bsel * KNc;
    const __nv_bfloat16* Blo = g_wlo + (size_t)bsel * KNc;
    float* dst = (dsel == 0) ? g_Q : (dsel == 1) ? g_K : (dsel == 2) ? g_V : outp;

    const uint32_t sb = smem_u32(smem);

    float acc[2][4][4];
    #pragma unroll
    for (int mt = 0; mt < 2; mt++)
        #pragma unroll
        for (int nt = 0; nt < 4; nt++)
            #pragma unroll
            for (int e = 0; e < 4; e++) acc[mt][nt][e] = 0.f;

    // ---- async load of one chunk into a stage ----
    auto load_stage = [&](int stage, int chunk) {
        const int k0 = chunk * BK;
        const uint32_t st = sb + stage * STAGE;
        #pragma unroll
        for (int p = 0; p < 6; p++) {
            int g = tid + p * 256;               // 0..1535
            if (g < 1024) {
                int sel = g >> 9;                // 0=Ahi 1=Alo
                int idx = g & 511;
                int row = idx >> 2, u = idx & 3;
                const __nv_bfloat16* src = sel ? Alo : Ahi;
                cp16(st + sel * 8192 + swz(row, u),
                     src + (size_t)(mBase + row) * DD + k0 + u * 8);
            } else {
                int sel = (g - 1024) >> 8;       // 0=Bhi 1=Blo
                int idx = (g - 1024) & 255;
                int row = idx >> 2, u = idx & 3;
                const __nv_bfloat16* src = sel ? Blo : Bhi;
                cp16(st + OFF_BHI + sel * 4096 + swz(row, u),
                     src + (size_t)(nBase + row) * DD + k0 + u * 8);
            }
        }
    };

    load_stage(0, 0);
    CP_COMMIT();

    for (int c = 0; c < NCHUNK; c++) {
        if (c + 1 < NCHUNK) {
            load_stage((c + 1) & 1, c + 1);
            CP_COMMIT();
            CP_WAIT(1);
        } else {
            CP_WAIT(0);
        }
        __syncthreads();

        const uint32_t st = sb + (c & 1) * STAGE;
        #pragma unroll
        for (int kk = 0; kk < 2; kk++) {
            uint32_t ah[2][4], al[2][4], bh[4][2], bl[4][2];
            int arow = warpM * 32 + (lane & 15);
            int au = kk * 2 + (lane >> 4);
            #pragma unroll
            for (int mt = 0; mt < 2; mt++) {
                uint32_t off = swz(arow + mt * 16, au);
                ldsm4(ah[mt], st + OFF_AHI + off);
                ldsm4(al[mt], st + OFF_ALO + off);
            }
            int brow = warpN * 32 + (lane & 7);
            int bu = kk * 2 + ((lane >> 3) & 1);
            #pragma unroll
            for (int nt = 0; nt < 4; nt++) {
                uint32_t off = swz(brow + nt * 8, bu);
                ldsm2(bh[nt], st + OFF_BHI + off);
                ldsm2(bl[nt], st + OFF_BLO + off);
            }
            #pragma unroll
            for (int mt = 0; mt < 2; mt++)
                #pragma unroll
                for (int nt = 0; nt < 4; nt++) {
                    mma16816(acc[mt][nt], ah[mt], bh[nt]);
                    mma16816(acc[mt][nt], ah[mt], bl[nt]);
                    mma16816(acc[mt][nt], al[mt], bh[nt]);
                }
        }
        __syncthreads();
    }

    // ---- epilogue: bias + (optional) head-permute store ----
    #pragma unroll
    for (int mt = 0; mt < 2; mt++) {
        #pragma unroll
        for (int nt = 0; nt < 4; nt++) {
            int colb = nBase + warpN * 32 + nt * 8 + (lane & 3) * 2;
            #pragma unroll
            for (int h2 = 0; h2 < 2; h2++) {
                int row = mBase + warpM * 32 + mt * 16 + (lane >> 2) + h2 * 8;
                int b = row >> 11;
                int s = row & 2047;
                #pragma unroll
                for (int e = 0; e < 2; e++) {
                    int n = colb + e;
                    float v = acc[mt][nt][h2 * 2 + e] + bias[n];
                    if (dsel < 3) {
                        int h = n & 15, dk = n >> 4;
                        dst[((size_t)(b * HH + h) * SS + s) * DK + dk] = v;
                    } else {
                        dst[(size_t)row * DD + n] = v;
                    }
                }
            }
        }
    }
}

// ---------------------------------------------------------------------------
// Causal flash attention (fp32 path)
// ---------------------------------------------------------------------------
#define ATT_SMEM_FLOATS (64*64 + 64*65 + 64*65 + 64*64)

__global__ __launch_bounds__(256) void attn_kernel()
{
    extern __shared__ float sm[];
    float* Qs = sm;
    float* Ks = Qs + 64 * 64;
    float* Vs = Ks + 64 * 65;
    float* Ps = Vs + 64 * 65;

    const int bh = blockIdx.y;
    const int qt = blockIdx.x;
    const float* Qb = g_Q + (size_t)bh * SS * DK;
    const float* Kb = g_K + (size_t)bh * SS * DK;
    const float* Vb = g_V + (size_t)bh * SS * DK;

    const int tid = threadIdx.x;
    const int ty = tid >> 4;
    const int tx = tid & 15;
    const int r0 = ty * 4;
    const int c0 = tx * 4;

    for (int e = tid; e < 64 * 64; e += 256) {
        int r = e >> 6, c = e & 63;
        Qs[r * 64 + c] = Qb[(size_t)(qt * 64 + r) * DK + c];
    }

    float mi[4], li[4], O[4][4];
    #pragma unroll
    for (int i = 0; i < 4; i++) {
        mi[i] = -INFINITY; li[i] = 0.f;
        #pragma unroll
        for (int j = 0; j < 4; j++) O[i][j] = 0.f;
    }

    const float scale = 0.125f;

    for (int kt = 0; kt <= qt; kt++) {
        __syncthreads();
        for (int e = tid; e < 64 * 64; e += 256) {
            int r = e >> 6, c = e & 63;
            Ks[r * 65 + c] = Kb[(size_t)(kt * 64 + r) * DK + c];
            Vs[r * 65 + c] = Vb[(size_t)(kt * 64 + r) * DK + c];
        }
        __syncthreads();

        float sc[4][4];
        #pragma unroll
        for (int i = 0; i < 4; i++)
            #pragma unroll
            for (int j = 0; j < 4; j++) sc[i][j] = 0.f;

        #pragma unroll 8
        for (int kk = 0; kk < 64; kk++) {
            float qv[4], kv[4];
            #pragma unroll
            for (int i = 0; i < 4; i++) qv[i] = Qs[(r0 + i) * 64 + kk];
            #pragma unroll
            for (int j = 0; j < 4; j++) kv[j] = Ks[(c0 + j) * 65 + kk];
            #pragma unroll
            for (int i = 0; i < 4; i++)
                #pragma unroll
                for (int j = 0; j < 4; j++)
                    sc[i][j] = fmaf(qv[i], kv[j], sc[i][j]);
        }

        const bool diag = (kt == qt);
        #pragma unroll
        for (int i = 0; i < 4; i++) {
            int qg = qt * 64 + r0 + i;
            #pragma unroll
            for (int j = 0; j < 4; j++) {
                int kg = kt * 64 + c0 + j;
                float v = sc[i][j] * scale;
                if (diag && kg > qg) v = -INFINITY;
                sc[i][j] = v;
            }
        }

        #pragma unroll
        for (int i = 0; i < 4; i++) {
            float rm = sc[i][0];
            #pragma unroll
            for (int j = 1; j < 4; j++) rm = fmaxf(rm, sc[i][j]);
            #pragma unroll
            for (int o = 8; o > 0; o >>= 1)
                rm = fmaxf(rm, __shfl_xor_sync(0xffffffffu, rm, o, 16));
            float mn = fmaxf(mi[i], rm);
            float alpha = __expf(mi[i] - mn);
            float rs = 0.f;
            #pragma unroll
            for (int j = 0; j < 4; j++) {
                float p = __expf(sc[i][j] - mn);
                sc[i][j] = p;
                rs += p;
            }
            #pragma unroll
            for (int o = 8; o > 0; o >>= 1)
                rs += __shfl_xor_sync(0xffffffffu, rs, o, 16);
            li[i] = li[i] * alpha + rs;
            mi[i] = mn;
            #pragma unroll
            for (int j = 0; j < 4; j++) O[i][j] *= alpha;
        }

        #pragma unroll
        for (int i = 0; i < 4; i++)
            #pragma unroll
            for (int j = 0; j < 4; j++)
                Ps[(r0 + i) * 64 + (c0 + j)] = sc[i][j];
        __syncthreads();

        #pragma unroll 8
        for (int kk = 0; kk < 64; kk++) {
            float pv[4], vv[4];
            #pragma unroll
            for (int i = 0; i < 4; i++) pv[i] = Ps[(r0 + i) * 64 + kk];
            #pragma unroll
            for (int j = 0; j < 4; j++) vv[j] = Vs[kk * 65 + (c0 + j)];
            #pragma unroll
            for (int i = 0; i < 4; i++)
                #pragma unroll
                for (int j = 0; j < 4; j++)
                    O[i][j] = fmaf(pv[i], vv[j], O[i][j]);
        }
    }

    const int b = bh >> 4;
    const int h = bh & 15;
    #pragma unroll
    for (int i = 0; i < 4; i++) {
        int qg = qt * 64 + r0 + i;
        float inv = 1.0f / li[i];
        #pragma unroll
        for (int j = 0; j < 4; j++) {
            g_C[((size_t)b * SS + qg) * DD + h * DK + (c0 + j)] = O[i][j] * inv;
        }
    }
}

// ---------------------------------------------------------------------------
extern "C" void kernel_launch(void* const* d_in, const int* in_sizes, int n_in,
                              void* d_out, int out_size)
{
    const float* q   = (const float*)d_in[0];
    const float* k   = (const float*)d_in[1];
    const float* v   = (const float*)d_in[2];
    // d_in[3] = mask (causal tril; handled in-kernel)
    const float* w_q = (const float*)d_in[4];
    const float* b_q = (const float*)d_in[5];
    const float* w_k = (const float*)d_in[6];
    const float* b_k = (const float*)d_in[7];
    const float* w_v = (const float*)d_in[8];
    const float* b_v = (const float*)d_in[9];
    const float* w_o = (const float*)d_in[10];
    const float* b_o = (const float*)d_in[11];
    float* out = (float*)d_out;

    // 0) split fp32 -> bf16 hi/lo
    {
        int n4a = (int)(MKc / 4);
        int n4w = (int)(KNc / 4);
        int tb = 256;
        split_kernel<<<(n4a + tb - 1) / tb, tb>>>(q, 0, 0 * MKc, n4a);
        split_kernel<<<(n4a + tb - 1) / tb, tb>>>(k, 0, 1 * MKc, n4a);
        split_kernel<<<(n4a + tb - 1) / tb, tb>>>(v, 0, 2 * MKc, n4a);
        split_kernel<<<(n4w + tb - 1) / tb, tb>>>(w_q, 1, 0 * KNc, n4w);
        split_kernel<<<(n4w + tb - 1) / tb, tb>>>(w_k, 1, 1 * KNc, n4w);
        split_kernel<<<(n4w + tb - 1) / tb, tb>>>(w_v, 1, 2 * KNc, n4w);
        split_kernel<<<(n4w + tb - 1) / tb, tb>>>(w_o, 1, 3 * KNc, n4w);
    }

    // 1) QKV projections on HMMA (bf16x3)
    dim3 gg(DD / BN, MTOT / BM);     // (16, 64)
    hmma_gemm_kernel<<<gg, 256>>>(0, 0, 0, b_q, nullptr);
    hmma_gemm_kernel<<<gg, 256>>>(1, 1, 1, b_k, nullptr);
    hmma_gemm_kernel<<<gg, 256>>>(2, 2, 2, b_v, nullptr);

    // 2) causal flash attention
    size_t smem = (size_t)ATT_SMEM_FLOATS * sizeof(float);
    cudaFuncSetAttribute(attn_kernel,
                         cudaFuncAttributeMaxDynamicSharedMemorySize, (int)smem);
    attn_kernel<<<dim3(SS / 64, BB * HH), 256, smem>>>();

    // 3) split context, then output projection on HMMA
    {
        int n4c = (int)(MKc / 4);
        split_kernel<<<(n4c + 255) / 256, 256>>>(nullptr, 2, 0, n4c);
    }
    hmma_gemm_kernel<<<gg, 256>>>(3, 3, 3, b_o, out);
}

// round 4
// speedup vs baseline: 2.3220x; 1.4515x over previous
#include <cuda_runtime.h>
#include <cuda_bf16.h>
#include <math.h>
#include <stdint.h>

// Problem dims
#define BB 4
#define SS 2048
#define DD 1024
#define HH 16
#define DK 64
#define MTOT (BB*SS)          // 8192

constexpr size_t MKc = (size_t)MTOT * DD;   // 8388608
constexpr size_t KNc = (size_t)DD * DD;     // 1048576
constexpr size_t HSZ = (size_t)BB * HH * SS * DK;  // 8388608

// 0.125 * log2(e): folds attention scale + exp->exp2 conversion into Q
#define QSCALE 0.18033688011112042f

// ---------------- scratch (__device__ globals; no allocs allowed) ----------
__device__ __nv_bfloat16 g_ahi[3*MKc];       // q,k,v inputs (GEMM A)
__device__ __nv_bfloat16 g_alo[3*MKc];
__device__ __nv_bfloat16 g_whi[4*KNc];       // wq,wk,wv,wo
__device__ __nv_bfloat16 g_wlo[4*KNc];
__device__ __nv_bfloat16 g_chi[MKc];         // context hi/lo (oproj A)
__device__ __nv_bfloat16 g_clo[MKc];
// projected q/k/v hi/lo in [b,h,s,dk]; q pre-scaled by QSCALE
__device__ __nv_bfloat16 g_qhi[HSZ], g_qlo[HSZ];
__device__ __nv_bfloat16 g_khi[HSZ], g_klo[HSZ];
__device__ __nv_bfloat16 g_vhi[HSZ], g_vlo[HSZ];

// ---------------- PTX helpers ---------------------------------------------
__device__ __forceinline__ uint32_t smem_u32(const void* p) {
    uint32_t a;
    asm("{ .reg .u64 t; cvta.to.shared.u64 t, %1; cvt.u32.u64 %0, t; }"
        : "=r"(a) : "l"(p));
    return a;
}

__device__ __forceinline__ void cp16(uint32_t s, const void* g) {
    asm volatile("cp.async.cg.shared.global [%0], [%1], 16;" :: "r"(s), "l"(g));
}
#define CP_COMMIT() asm volatile("cp.async.commit_group;" ::: "memory")
#define CP_WAIT(n)  asm volatile("cp.async.wait_group %0;" :: "n"(n) : "memory")

__device__ __forceinline__ void ldsm4(uint32_t* r, uint32_t addr) {
    asm volatile("ldmatrix.sync.aligned.m8n8.x4.shared.b16 {%0,%1,%2,%3}, [%4];"
                 : "=r"(r[0]), "=r"(r[1]), "=r"(r[2]), "=r"(r[3]) : "r"(addr));
}
__device__ __forceinline__ void ldsm4t(uint32_t* r, uint32_t addr) {
    asm volatile("ldmatrix.sync.aligned.m8n8.x4.trans.shared.b16 {%0,%1,%2,%3}, [%4];"
                 : "=r"(r[0]), "=r"(r[1]), "=r"(r[2]), "=r"(r[3]) : "r"(addr));
}
__device__ __forceinline__ void ldsm2(uint32_t* r, uint32_t addr) {
    asm volatile("ldmatrix.sync.aligned.m8n8.x2.shared.b16 {%0,%1}, [%2];"
                 : "=r"(r[0]), "=r"(r[1]) : "r"(addr));
}
__device__ __forceinline__ void mma16816(float* c, const uint32_t* a, const uint32_t* b) {
    asm volatile("mma.sync.aligned.m16n8k16.row.col.f32.bf16.bf16.f32 "
                 "{%0,%1,%2,%3}, {%4,%5,%6,%7}, {%8,%9}, {%0,%1,%2,%3};"
                 : "+f"(c[0]), "+f"(c[1]), "+f"(c[2]), "+f"(c[3])
                 : "r"(a[0]), "r"(a[1]), "r"(a[2]), "r"(a[3]),
                   "r"(b[0]), "r"(b[1]));
}

// GEMM smem swizzle: 64B rows (4x16B units)
__device__ __forceinline__ uint32_t swz(int row, int u) {
    return (uint32_t)(row * 64 + ((u ^ ((row >> 1) & 3)) << 4));
}
// Attention smem swizzle: 128B rows (8x16B units)
__device__ __forceinline__ uint32_t swzV(int row, int u) {
    return (uint32_t)(row * 128 + ((u ^ (row & 7)) << 4));
}

// fast 2^t on FMA/ALU pipes (no MUFU). t <= ~0; clamped at -126.
__device__ __forceinline__ float fexp2(float t) {
    t = fmaxf(t, -126.f);
    float tt = t + 12582912.f;              // round-to-nearest-int trick
    float fi = tt - 12582912.f;
    float f  = t - fi;                      // [-0.5, 0.5]
    int   ei = __float_as_int(tt) - 0x4B400000;
    float sc = __int_as_float((ei + 127) << 23);
    float p = fmaf(f, 1.33335581e-3f, 9.61812911e-3f);
    p = fmaf(f, p, 5.55041087e-2f);
    p = fmaf(f, p, 2.40226507e-1f);
    p = fmaf(f, p, 6.93147181e-1f);
    p = fmaf(f, p, 1.0f);
    return sc * p;
}

__device__ __forceinline__ uint32_t packbf2(float f0, float f1) {
    __nv_bfloat162 h = __floats2bfloat162_rn(f0, f1);
    return *(uint32_t*)&h;
}
__device__ __forceinline__ uint32_t packbf2_res(float f0, float f1, float& r0, float& r1) {
    __nv_bfloat162 h = __floats2bfloat162_rn(f0, f1);
    r0 = f0 - __bfloat162float(__low2bfloat16(h));
    r1 = f1 - __bfloat162float(__high2bfloat16(h));
    return *(uint32_t*)&h;
}

// ---------------------------------------------------------------------------
// split kernel: fp32 -> bf16 hi + lo.  which: 0=inputs, 1=weights
// ---------------------------------------------------------------------------
__global__ __launch_bounds__(256) void split_kernel(const float* __restrict__ src,
                                                    int which, size_t off, int n4)
{
    int i = blockIdx.x * blockDim.x + threadIdx.x;
    if (i >= n4) return;
    __nv_bfloat16 *hi, *lo;
    if (which == 0) { hi = g_ahi + off; lo = g_alo + off; }
    else            { hi = g_whi + off; lo = g_wlo + off; }
    float4 x = ((const float4*)src)[i];
    float v0 = x.x, v1 = x.y, v2 = x.z, v3 = x.w;
    __nv_bfloat16 h0 = __float2bfloat16(v0), h1 = __float2bfloat16(v1);
    __nv_bfloat16 h2 = __float2bfloat16(v2), h3 = __float2bfloat16(v3);
    __nv_bfloat16 l0 = __float2bfloat16(v0 - __bfloat162float(h0));
    __nv_bfloat16 l1 = __float2bfloat16(v1 - __bfloat162float(h1));
    __nv_bfloat16 l2 = __float2bfloat16(v2 - __bfloat162float(h2));
    __nv_bfloat16 l3 = __float2bfloat16(v3 - __bfloat162float(h3));
    ((__nv_bfloat162*)hi)[2*i + 0] = __halves2bfloat162(h0, h1);
    ((__nv_bfloat162*)hi)[2*i + 1] = __halves2bfloat162(h2, h3);
    ((__nv_bfloat162*)lo)[2*i + 0] = __halves2bfloat162(l0, l1);
    ((__nv_bfloat162*)lo)[2*i + 1] = __halves2bfloat162(l2, l3);
}

// ---------------------------------------------------------------------------
// HMMA bf16x3 GEMM: Y = A(Mx1024) @ W(Nx1024)^T + bias
// CTA tile 128x64, BK=32, 8 warps (4M x 2N). Double-buffered cp.async.
// dsel 0/1/2: write bf16 hi/lo to g_{q,k,v}{hi,lo} [b,h,s,dk] (q scaled)
// dsel 3:     write fp32 row-major to outp
// ---------------------------------------------------------------------------
#define BM 128
#define BN 64
#define BK 32
#define NCHUNK (DD / BK)     // 32
#define OFF_AHI 0
#define OFF_ALO 8192
#define OFF_BHI 16384
#define OFF_BLO 20480
#define STAGE   24576

__global__ __launch_bounds__(256, 2)
void hmma_gemm_kernel(int asel, int bsel, int dsel,
                      const float* __restrict__ bias, float* __restrict__ outp)
{
    __shared__ char smem[2 * STAGE];     // 48KB

    const int tid = threadIdx.x;
    const int wid = tid >> 5;
    const int lane = tid & 31;
    const int warpM = wid & 3;
    const int warpN = wid >> 2;
    const int mBase = blockIdx.y * BM;
    const int nBase = blockIdx.x * BN;

    const __nv_bfloat16 *Ahi, *Alo;
    if (asel < 3) { Ahi = g_ahi + (size_t)asel * MKc; Alo = g_alo + (size_t)asel * MKc; }
    else          { Ahi = g_chi; Alo = g_clo; }
    const __nv_bfloat16* Bhi = g_whi + (size_t)bsel * KNc;
    const __nv_bfloat16* Blo = g_wlo + (size_t)bsel * KNc;

    const uint32_t sb = smem_u32(smem);

    float acc[2][4][4];
    #pragma unroll
    for (int mt = 0; mt < 2; mt++)
        #pragma unroll
        for (int nt = 0; nt < 4; nt++)
            #pragma unroll
            for (int e = 0; e < 4; e++) acc[mt][nt][e] = 0.f;

    auto load_stage = [&](int stage, int chunk) {
        const int k0 = chunk * BK;
        const uint32_t st = sb + stage * STAGE;
        #pragma unroll
        for (int p = 0; p < 6; p++) {
            int g = tid + p * 256;
            if (g < 1024) {
                int sel = g >> 9;
                int idx = g & 511;
                int row = idx >> 2, u = idx & 3;
                const __nv_bfloat16* src = sel ? Alo : Ahi;
                cp16(st + sel * 8192 + swz(row, u),
                     src + (size_t)(mBase + row) * DD + k0 + u * 8);
            } else {
                int sel = (g - 1024) >> 8;
                int idx = (g - 1024) & 255;
                int row = idx >> 2, u = idx & 3;
                const __nv_bfloat16* src = sel ? Blo : Bhi;
                cp16(st + OFF_BHI + sel * 4096 + swz(row, u),
                     src + (size_t)(nBase + row) * DD + k0 + u * 8);
            }
        }
    };

    load_stage(0, 0);
    CP_COMMIT();

    for (int c = 0; c < NCHUNK; c++) {
        if (c + 1 < NCHUNK) {
            load_stage((c + 1) & 1, c + 1);
            CP_COMMIT();
            CP_WAIT(1);
        } else {
            CP_WAIT(0);
        }
        __syncthreads();

        const uint32_t st = sb + (c & 1) * STAGE;
        #pragma unroll
        for (int kk = 0; kk < 2; kk++) {
            uint32_t ah[2][4], al[2][4], bh[4][2], bl[4][2];
            int arow = warpM * 32 + (lane & 15);
            int au = kk * 2 + (lane >> 4);
            #pragma unroll
            for (int mt = 0; mt < 2; mt++) {
                uint32_t off = swz(arow + mt * 16, au);
                ldsm4(ah[mt], st + OFF_AHI + off);
                ldsm4(al[mt], st + OFF_ALO + off);
            }
            int brow = warpN * 32 + (lane & 7);
            int bu = kk * 2 + ((lane >> 3) & 1);
            #pragma unroll
            for (int nt = 0; nt < 4; nt++) {
                uint32_t off = swz(brow + nt * 8, bu);
                ldsm2(bh[nt], st + OFF_BHI + off);
                ldsm2(bl[nt], st + OFF_BLO + off);
            }
            #pragma unroll
            for (int mt = 0; mt < 2; mt++)
                #pragma unroll
                for (int nt = 0; nt < 4; nt++) {
                    mma16816(acc[mt][nt], ah[mt], bh[nt]);
                    mma16816(acc[mt][nt], ah[mt], bl[nt]);
                    mma16816(acc[mt][nt], al[mt], bh[nt]);
                }
        }
        __syncthreads();
    }

    // epilogue
    const float scl = (dsel == 0) ? QSCALE : 1.f;
    __nv_bfloat16 *hiA = nullptr, *loA = nullptr;
    if (dsel == 0) { hiA = g_qhi; loA = g_qlo; }
    else if (dsel == 1) { hiA = g_khi; loA = g_klo; }
    else if (dsel == 2) { hiA = g_vhi; loA = g_vlo; }

    #pragma unroll
    for (int mt = 0; mt < 2; mt++) {
        #pragma unroll
        for (int nt = 0; nt < 4; nt++) {
            int colb = nBase + warpN * 32 + nt * 8 + (lane & 3) * 2;
            #pragma unroll
            for (int h2 = 0; h2 < 2; h2++) {
                int row = mBase + warpM * 32 + mt * 16 + (lane >> 2) + h2 * 8;
                int b = row >> 11;
                int s = row & 2047;
                #pragma unroll
                for (int e = 0; e < 2; e++) {
                    int n = colb + e;
                    float v = acc[mt][nt][h2 * 2 + e] + bias[n];
                    if (dsel < 3) {
                        v *= scl;
                        int h = n & 15, dk = n >> 4;
                        size_t adr = ((size_t)(b * HH + h) * SS + s) * DK + dk;
                        __nv_bfloat16 hv = __float2bfloat16(v);
                        hiA[adr] = hv;
                        loA[adr] = __float2bfloat16(v - __bfloat162float(hv));
                    } else {
                        outp[(size_t)row * DD + n] = v;
                    }
                }
            }
        }
    }
}

// ---------------------------------------------------------------------------
// HMMA flash attention, causal. CTA: 64 q-rows, 4 warps (16 rows each).
// Q pre-scaled by 0.125*log2e -> scores in log2 domain; fexp2 on FMA pipe.
// 3-pass hi/lo for both S=QK^T and O=PV.
// smem: K hi/lo + V hi/lo tiles, 64x64 bf16 each, 128B-row swizzle. 32KB.
// ---------------------------------------------------------------------------
#define AT_KHI 0
#define AT_KLO 8192
#define AT_VHI 16384
#define AT_VLO 24576

__global__ __launch_bounds__(128) void fattn_kernel()
{
    __shared__ char smem[32768];
    const uint32_t sb = smem_u32(smem);

    const int tid  = threadIdx.x;
    const int wid  = tid >> 5;
    const int lane = tid & 31;
    const int g    = lane >> 2;          // row group 0..7
    const int tq   = lane & 3;           // col pair idx 0..3
    const int bh   = blockIdx.y;
    const int qt   = gridDim.x - 1 - blockIdx.x;   // longest first

    const size_t hb = (size_t)bh * SS * DK;
    const __nv_bfloat16* Qhi = g_qhi + hb;
    const __nv_bfloat16* Qlo = g_qlo + hb;
    const __nv_bfloat16* Khi = g_khi + hb;
    const __nv_bfloat16* Klo = g_klo + hb;
    const __nv_bfloat16* Vhi = g_vhi + hb;
    const __nv_bfloat16* Vlo = g_vlo + hb;

    // ---- stage Q tile (64x64) into K slots, pull frags to regs ----
    #pragma unroll
    for (int p = 0; p < 4; p++) {
        int idx = tid + p * 128;
        int row = idx >> 3, u = idx & 7;
        size_t go = (size_t)(qt * 64 + row) * DK + u * 8;
        uint32_t s = swzV(row, u);
        cp16(sb + AT_KHI + s, Qhi + go);
        cp16(sb + AT_KLO + s, Qlo + go);
    }
    CP_COMMIT(); CP_WAIT(0);
    __syncthreads();

    uint32_t qh[4][4], ql[4][4];
    {
        int arow = wid * 16 + (lane & 15);
        int au = lane >> 4;
        #pragma unroll
        for (int ch = 0; ch < 4; ch++) {
            uint32_t off = swzV(arow, ch * 2 + au);
            ldsm4(qh[ch], sb + AT_KHI + off);
            ldsm4(ql[ch], sb + AT_KLO + off);
        }
    }
    __syncthreads();

    float o[8][4];
    #pragma unroll
    for (int m = 0; m < 8; m++)
        #pragma unroll
        for (int e = 0; e < 4; e++) o[m][e] = 0.f;
    float m1 = -1e30f, m2 = -1e30f, l1 = 0.f, l2 = 0.f;

    // per-thread address components
    const int rB = ((lane >> 4) << 3) + (lane & 7);   // K-frag row offset
    const int uB = (lane >> 3) & 1;                   // K-frag unit offset
    const int rV = (((lane >> 3) & 1) << 3) + (lane & 7); // V-frag row offset
    const int uV = lane >> 4;                         // V-frag unit offset

    for (int kt = 0; kt <= qt; kt++) {
        __syncthreads();   // everyone done with previous K/V smem
        #pragma unroll
        for (int p = 0; p < 4; p++) {
            int idx = tid + p * 128;
            int row = idx >> 3, u = idx & 7;
            size_t go = (size_t)(kt * 64 + row) * DK + u * 8;
            uint32_t s = swzV(row, u);
            cp16(sb + AT_KHI + s, Khi + go);
            cp16(sb + AT_KLO + s, Klo + go);
            cp16(sb + AT_VHI + s, Vhi + go);
            cp16(sb + AT_VLO + s, Vlo + go);
        }
        CP_COMMIT(); CP_WAIT(0);
        __syncthreads();

        // ---- S = Q @ K^T (3-pass hi/lo) ----
        float s[8][4];
        #pragma unroll
        for (int m = 0; m < 8; m++)
            #pragma unroll
            for (int e = 0; e < 4; e++) s[m][e] = 0.f;

        #pragma unroll
        for (int ch = 0; ch < 4; ch++) {
            uint32_t kh[4][4], kl[4][4];
            #pragma unroll
            for (int p = 0; p < 4; p++) {
                uint32_t off = swzV(p * 16 + rB, ch * 2 + uB);
                ldsm4(kh[p], sb + AT_KHI + off);
                ldsm4(kl[p], sb + AT_KLO + off);
            }
            #pragma unroll
            for (int p = 0; p < 4; p++) {
                mma16816(s[2*p],   qh[ch], &kh[p][0]);
                mma16816(s[2*p],   qh[ch], &kl[p][0]);
                mma16816(s[2*p],   ql[ch], &kh[p][0]);
                mma16816(s[2*p+1], qh[ch], &kh[p][2]);
                mma16816(s[2*p+1], qh[ch], &kl[p][2]);
                mma16816(s[2*p+1], ql[ch], &kh[p][2]);
            }
        }

        // ---- causal mask on diagonal block ----
        if (kt == qt) {
            int rowA = wid * 16 + g;       // local row 1
            int rowBr = rowA + 8;          // local row 2
            #pragma unroll
            for (int m = 0; m < 8; m++) {
                int c0 = m * 8 + tq * 2;
                if (c0     > rowA)  s[m][0] = -1e30f;
                if (c0 + 1 > rowA)  s[m][1] = -1e30f;
                if (c0     > rowBr) s[m][2] = -1e30f;
                if (c0 + 1 > rowBr) s[m][3] = -1e30f;
            }
        }

        // ---- online softmax (log2 domain) ----
        float mx1 = -1e30f, mx2 = -1e30f;
        #pragma unroll
        for (int m = 0; m < 8; m++) {
            mx1 = fmaxf(mx1, fmaxf(s[m][0], s[m][1]));
            mx2 = fmaxf(mx2, fmaxf(s[m][2], s[m][3]));
        }
        mx1 = fmaxf(mx1, __shfl_xor_sync(0xffffffffu, mx1, 1));
        mx1 = fmaxf(mx1, __shfl_xor_sync(0xffffffffu, mx1, 2));
        mx2 = fmaxf(mx2, __shfl_xor_sync(0xffffffffu, mx2, 1));
        mx2 = fmaxf(mx2, __shfl_xor_sync(0xffffffffu, mx2, 2));
        float nm1 = fmaxf(m1, mx1), nm2 = fmaxf(m2, mx2);
        float a1 = fexp2(m1 - nm1), a2 = fexp2(m2 - nm2);
        float r1 = 0.f, r2 = 0.f;
        #pragma unroll
        for (int m = 0; m < 8; m++) {
            s[m][0] = fexp2(s[m][0] - nm1);
            s[m][1] = fexp2(s[m][1] - nm1);
            s[m][2] = fexp2(s[m][2] - nm2);
            s[m][3] = fexp2(s[m][3] - nm2);
            r1 += s[m][0] + s[m][1];
            r2 += s[m][2] + s[m][3];
        }
        r1 += __shfl_xor_sync(0xffffffffu, r1, 1);
        r1 += __shfl_xor_sync(0xffffffffu, r1, 2);
        r2 += __shfl_xor_sync(0xffffffffu, r2, 1);
        r2 += __shfl_xor_sync(0xffffffffu, r2, 2);
        l1 = l1 * a1 + r1;
        l2 = l2 * a2 + r2;
        m1 = nm1; m2 = nm2;
        #pragma unroll
        for (int m = 0; m < 8; m++) {
            o[m][0] *= a1; o[m][1] *= a1;
            o[m][2] *= a2; o[m][3] *= a2;
        }

        // ---- P fragments (hi/lo) in registers ----
        uint32_t ph[4][4], pl[4][4];
        #pragma unroll
        for (int jc = 0; jc < 4; jc++) {
            float d0, d1;
            ph[jc][0] = packbf2_res(s[2*jc][0],   s[2*jc][1],   d0, d1);
            pl[jc][0] = packbf2(d0, d1);
            ph[jc][1] = packbf2_res(s[2*jc][2],   s[2*jc][3],   d0, d1);
            pl[jc][1] = packbf2(d0, d1);
            ph[jc][2] = packbf2_res(s[2*jc+1][0], s[2*jc+1][1], d0, d1);
            pl[jc][2] = packbf2(d0, d1);
            ph[jc][3] = packbf2_res(s[2*jc+1][2], s[2*jc+1][3], d0, d1);
            pl[jc][3] = packbf2(d0, d1);
        }

        // ---- O += P @ V (3-pass hi/lo) ----
        #pragma unroll
        for (int jc = 0; jc < 4; jc++) {
            uint32_t vh[4][4], vl[4][4];
            #pragma unroll
            for (int dp = 0; dp < 4; dp++) {
                uint32_t off = swzV(jc * 16 + rV, 2 * dp + uV);
                ldsm4t(vh[dp], sb + AT_VHI + off);
                ldsm4t(vl[dp], sb + AT_VLO + off);
            }
            #pragma unroll
            for (int dp = 0; dp < 4; dp++) {
                mma16816(o[2*dp],   ph[jc], &vh[dp][0]);
                mma16816(o[2*dp],   ph[jc], &vl[dp][0]);
                mma16816(o[2*dp],   pl[jc], &vh[dp][0]);
                mma16816(o[2*dp+1], ph[jc], &vh[dp][2]);
                mma16816(o[2*dp+1], ph[jc], &vl[dp][2]);
                mma16816(o[2*dp+1], pl[jc], &vh[dp][2]);
            }
        }
    }

    // ---- epilogue: write context hi/lo at [b, s, h*64 + d] ----
    const float inv1 = 1.f / l1, inv2 = 1.f / l2;
    const int b = bh >> 4;
    const int h = bh & 15;
    const int sg1 = qt * 64 + wid * 16 + g;
    const int sg2 = sg1 + 8;
    #pragma unroll
    for (int m = 0; m < 8; m++) {
        int col = h * 64 + m * 8 + tq * 2;
        size_t a1i = ((size_t)(b * SS + sg1) * DD + col) >> 1;  // bf162 index
        size_t a2i = ((size_t)(b * SS + sg2) * DD + col) >> 1;
        float f0 = o[m][0] * inv1, f1 = o[m][1] * inv1;
        float f2 = o[m][2] * inv2, f3 = o[m][3] * inv2;
        float d0, d1;
        uint32_t hi1 = packbf2_res(f0, f1, d0, d1);
        uint32_t lo1 = packbf2(d0, d1);
        uint32_t hi2 = packbf2_res(f2, f3, d0, d1);
        uint32_t lo2 = packbf2(d0, d1);
        ((uint32_t*)g_chi)[a1i] = hi1;
        ((uint32_t*)g_clo)[a1i] = lo1;
        ((uint32_t*)g_chi)[a2i] = hi2;
        ((uint32_t*)g_clo)[a2i] = lo2;
    }
}

// ---------------------------------------------------------------------------
extern "C" void kernel_launch(void* const* d_in, const int* in_sizes, int n_in,
                              void* d_out, int out_size)
{
    const float* q   = (const float*)d_in[0];
    const float* k   = (const float*)d_in[1];
    const float* v   = (const float*)d_in[2];
    // d_in[3] = mask (causal tril; handled in-kernel)
    const float* w_q = (const float*)d_in[4];
    const float* b_q = (const float*)d_in[5];
    const float* w_k = (const float*)d_in[6];
    const float* b_k = (const float*)d_in[7];
    const float* w_v = (const float*)d_in[8];
    const float* b_v = (const float*)d_in[9];
    const float* w_o = (const float*)d_in[10];
    const float* b_o = (const float*)d_in[11];
    float* out = (float*)d_out;

    // 0) split fp32 -> bf16 hi/lo
    {
        int n4a = (int)(MKc / 4);
        int n4w = (int)(KNc / 4);
        int tb = 256;
        split_kernel<<<(n4a + tb - 1) / tb, tb>>>(q, 0, 0 * MKc, n4a);
        split_kernel<<<(n4a + tb - 1) / tb, tb>>>(k, 0, 1 * MKc, n4a);
        split_kernel<<<(n4a + tb - 1) / tb, tb>>>(v, 0, 2 * MKc, n4a);
        split_kernel<<<(n4w + tb - 1) / tb, tb>>>(w_q, 1, 0 * KNc, n4w);
        split_kernel<<<(n4w + tb - 1) / tb, tb>>>(w_k, 1, 1 * KNc, n4w);
        split_kernel<<<(n4w + tb - 1) / tb, tb>>>(w_v, 1, 2 * KNc, n4w);
        split_kernel<<<(n4w + tb - 1) / tb, tb>>>(w_o, 1, 3 * KNc, n4w);
    }

    // 1) QKV projections on HMMA (bf16x3), hi/lo epilogue
    dim3 gg(DD / BN, MTOT / BM);     // (16, 64)
    hmma_gemm_kernel<<<gg, 256>>>(0, 0, 0, b_q, nullptr);
    hmma_gemm_kernel<<<gg, 256>>>(1, 1, 1, b_k, nullptr);
    hmma_gemm_kernel<<<gg, 256>>>(2, 2, 2, b_v, nullptr);

    // 2) causal flash attention on HMMA
    fattn_kernel<<<dim3(SS / 64, BB * HH), 128>>>();

    // 3) output projection on HMMA (context hi/lo written by attention)
    hmma_gemm_kernel<<<gg, 256>>>(3, 3, 3, b_o, out);
}

// round 5
// speedup vs baseline: 2.3551x; 1.0143x over previous
#include <cuda_runtime.h>
#include <cuda_bf16.h>
#include <math.h>
#include <stdint.h>

// Problem dims
#define BB 4
#define SS 2048
#define DD 1024
#define HH 16
#define DK 64
#define MTOT (BB*SS)          // 8192

constexpr size_t MKc = (size_t)MTOT * DD;   // 8388608
constexpr size_t KNc = (size_t)DD * DD;     // 1048576
constexpr size_t HSZ = (size_t)BB * HH * SS * DK;  // 8388608

// 0.125 * log2(e): folds attention scale + exp->exp2 conversion into Q
#define QSCALE 0.18033688011112042f

// ---------------- scratch (__device__ globals; no allocs allowed) ----------
__device__ __nv_bfloat16 g_ahi[3*MKc];       // q,k,v inputs (GEMM A)
__device__ __nv_bfloat16 g_alo[3*MKc];
__device__ __nv_bfloat16 g_whi[4*KNc];       // wq,wk,wv,wo
__device__ __nv_bfloat16 g_wlo[4*KNc];
__device__ __nv_bfloat16 g_chi[MKc];         // context hi/lo (oproj A)
__device__ __nv_bfloat16 g_clo[MKc];
// projected q/k/v hi/lo in [b,h,s,dk]; q pre-scaled by QSCALE
__device__ __nv_bfloat16 g_qhi[HSZ], g_qlo[HSZ];
__device__ __nv_bfloat16 g_khi[HSZ], g_klo[HSZ];
__device__ __nv_bfloat16 g_vhi[HSZ], g_vlo[HSZ];

// ---------------- PTX helpers ---------------------------------------------
__device__ __forceinline__ uint32_t smem_u32(const void* p) {
    uint32_t a;
    asm("{ .reg .u64 t; cvta.to.shared.u64 t, %1; cvt.u32.u64 %0, t; }"
        : "=r"(a) : "l"(p));
    return a;
}

__device__ __forceinline__ void cp16(uint32_t s, const void* g) {
    asm volatile("cp.async.cg.shared.global [%0], [%1], 16;" :: "r"(s), "l"(g));
}
#define CP_COMMIT() asm volatile("cp.async.commit_group;" ::: "memory")
#define CP_WAIT(n)  asm volatile("cp.async.wait_group %0;" :: "n"(n) : "memory")

__device__ __forceinline__ void ldsm4(uint32_t* r, uint32_t addr) {
    asm volatile("ldmatrix.sync.aligned.m8n8.x4.shared.b16 {%0,%1,%2,%3}, [%4];"
                 : "=r"(r[0]), "=r"(r[1]), "=r"(r[2]), "=r"(r[3]) : "r"(addr));
}
__device__ __forceinline__ void ldsm4t(uint32_t* r, uint32_t addr) {
    asm volatile("ldmatrix.sync.aligned.m8n8.x4.trans.shared.b16 {%0,%1,%2,%3}, [%4];"
                 : "=r"(r[0]), "=r"(r[1]), "=r"(r[2]), "=r"(r[3]) : "r"(addr));
}
__device__ __forceinline__ void mma16816(float* c, const uint32_t* a, const uint32_t* b) {
    asm volatile("mma.sync.aligned.m16n8k16.row.col.f32.bf16.bf16.f32 "
                 "{%0,%1,%2,%3}, {%4,%5,%6,%7}, {%8,%9}, {%0,%1,%2,%3};"
                 : "+f"(c[0]), "+f"(c[1]), "+f"(c[2]), "+f"(c[3])
                 : "r"(a[0]), "r"(a[1]), "r"(a[2]), "r"(a[3]),
                   "r"(b[0]), "r"(b[1]));
}

// GEMM smem swizzle: 64B rows (4x16B units)
__device__ __forceinline__ uint32_t swz(int row, int u) {
    return (uint32_t)(row * 64 + ((u ^ ((row >> 1) & 3)) << 4));
}
// Attention smem swizzle: 128B rows (8x16B units)
__device__ __forceinline__ uint32_t swzV(int row, int u) {
    return (uint32_t)(row * 128 + ((u ^ (row & 7)) << 4));
}

// fast 2^t on FMA/ALU pipes (no MUFU). t <= ~0; clamped at -126.
__device__ __forceinline__ float fexp2(float t) {
    t = fmaxf(t, -126.f);
    float tt = t + 12582912.f;
    float fi = tt - 12582912.f;
    float f  = t - fi;
    int   ei = __float_as_int(tt) - 0x4B400000;
    float sc = __int_as_float((ei + 127) << 23);
    float p = fmaf(f, 1.33335581e-3f, 9.61812911e-3f);
    p = fmaf(f, p, 5.55041087e-2f);
    p = fmaf(f, p, 2.40226507e-1f);
    p = fmaf(f, p, 6.93147181e-1f);
    p = fmaf(f, p, 1.0f);
    return sc * p;
}

__device__ __forceinline__ uint32_t packbf2(float f0, float f1) {
    __nv_bfloat162 h = __floats2bfloat162_rn(f0, f1);
    return *(uint32_t*)&h;
}
__device__ __forceinline__ uint32_t packbf2_res(float f0, float f1, float& r0, float& r1) {
    __nv_bfloat162 h = __floats2bfloat162_rn(f0, f1);
    r0 = f0 - __bfloat162float(__low2bfloat16(h));
    r1 = f1 - __bfloat162float(__high2bfloat16(h));
    return *(uint32_t*)&h;
}

// ---------------------------------------------------------------------------
// fused split: all 3 inputs + 4 weights in ONE launch. fp32 -> bf16 hi + lo.
// blocks 0..24575: inputs (8192 blocks each); 24576..28671: weights (1024 each)
// ---------------------------------------------------------------------------
__global__ __launch_bounds__(256) void split_all_kernel(
    const float* __restrict__ q, const float* __restrict__ k, const float* __restrict__ v,
    const float* __restrict__ wq, const float* __restrict__ wk,
    const float* __restrict__ wv, const float* __restrict__ wo)
{
    const int bid = blockIdx.x;
    const float* src;
    __nv_bfloat16 *hi, *lo;
    int i;
    if (bid < 24576) {
        int r = bid >> 13;                 // /8192
        src = (r == 0) ? q : (r == 1) ? k : v;
        hi = g_ahi + (size_t)r * MKc;
        lo = g_alo + (size_t)r * MKc;
        i = ((bid & 8191) << 8) + threadIdx.x;
    } else {
        int t = bid - 24576;
        int r = t >> 10;                   // /1024
        src = (r == 0) ? wq : (r == 1) ? wk : (r == 2) ? wv : wo;
        hi = g_whi + (size_t)r * KNc;
        lo = g_wlo + (size_t)r * KNc;
        i = ((t & 1023) << 8) + threadIdx.x;
    }
    float4 x = ((const float4*)src)[i];
    float v0 = x.x, v1 = x.y, v2 = x.z, v3 = x.w;
    __nv_bfloat16 h0 = __float2bfloat16(v0), h1 = __float2bfloat16(v1);
    __nv_bfloat16 h2 = __float2bfloat16(v2), h3 = __float2bfloat16(v3);
    __nv_bfloat16 l0 = __float2bfloat16(v0 - __bfloat162float(h0));
    __nv_bfloat16 l1 = __float2bfloat16(v1 - __bfloat162float(h1));
    __nv_bfloat16 l2 = __float2bfloat16(v2 - __bfloat162float(h2));
    __nv_bfloat16 l3 = __float2bfloat16(v3 - __bfloat162float(h3));
    ((__nv_bfloat162*)hi)[2*i + 0] = __halves2bfloat162(h0, h1);
    ((__nv_bfloat162*)hi)[2*i + 1] = __halves2bfloat162(h2, h3);
    ((__nv_bfloat162*)lo)[2*i + 0] = __halves2bfloat162(l0, l1);
    ((__nv_bfloat162*)lo)[2*i + 1] = __halves2bfloat162(l2, l3);
}

// ---------------------------------------------------------------------------
// HMMA bf16x3 GEMM: Y = A(Mx1024) @ W(Nx1024)^T + bias
// CTA tile 128x128, BK=32, 8 warps as 2(M)x4(N), warp tile 64x32.
// Double-buffered cp.async (64KB dynamic smem).
// mode 0: QKV fused (blockIdx.z = 0/1/2 selects q/k/v); writes bf16 hi/lo
//         [b,h,s,dk] (q scaled by QSCALE).
// mode 1: oproj (A = context hi/lo); writes fp32 row-major to outp.
// ---------------------------------------------------------------------------
#define BM 128
#define BN 128
#define BK 32
#define NCHUNK (DD / BK)     // 32
#define GOFF_ALO 8192
#define GOFF_BHI 16384
#define GOFF_BLO 24576
#define GSTAGE   32768

__global__ __launch_bounds__(256, 1)
void hmma_gemm_kernel(int mode, const float* __restrict__ bq,
                      const float* __restrict__ bk, const float* __restrict__ bv,
                      float* __restrict__ outp)
{
    extern __shared__ char smem[];

    const int tid = threadIdx.x;
    const int wid = tid >> 5;
    const int lane = tid & 31;
    const int warpM = wid & 1;          // 0..1 -> 64 rows
    const int warpN = wid >> 1;         // 0..3 -> 32 cols
    const int mBase = blockIdx.y * BM;
    const int nBase = blockIdx.x * BN;
    const int z = blockIdx.z;

    const __nv_bfloat16 *Ahi, *Alo, *Bhi, *Blo;
    const float* bias;
    if (mode == 0) {
        Ahi = g_ahi + (size_t)z * MKc; Alo = g_alo + (size_t)z * MKc;
        Bhi = g_whi + (size_t)z * KNc; Blo = g_wlo + (size_t)z * KNc;
        bias = (z == 0) ? bq : (z == 1) ? bk : bv;
    } else {
        Ahi = g_chi; Alo = g_clo;
        Bhi = g_whi + 3 * KNc; Blo = g_wlo + 3 * KNc;
        bias = bq;
    }

    const uint32_t sb = smem_u32(smem);

    float acc[4][4][4];
    #pragma unroll
    for (int mt = 0; mt < 4; mt++)
        #pragma unroll
        for (int nt = 0; nt < 4; nt++)
            #pragma unroll
            for (int e = 0; e < 4; e++) acc[mt][nt][e] = 0.f;

    auto load_stage = [&](int stage, int chunk) {
        const int k0 = chunk * BK;
        const uint32_t st = sb + stage * GSTAGE;
        #pragma unroll
        for (int p = 0; p < 8; p++) {
            int g = tid + p * 256;               // 0..2047
            int part = (g >> 9) & 1;             // hi/lo
            int idx = g & 511;
            int row = idx >> 2, u = idx & 3;
            if (g < 1024) {
                const __nv_bfloat16* src = part ? Alo : Ahi;
                cp16(st + part * 8192 + swz(row, u),
                     src + (size_t)(mBase + row) * DD + k0 + u * 8);
            } else {
                const __nv_bfloat16* src = part ? Blo : Bhi;
                cp16(st + GOFF_BHI + part * 8192 + swz(row, u),
                     src + (size_t)(nBase + row) * DD + k0 + u * 8);
            }
        }
    };

    load_stage(0, 0);
    CP_COMMIT();

    const int rB = ((lane >> 4) << 3) + (lane & 7);
    const int uB = (lane >> 3) & 1;

    for (int c = 0; c < NCHUNK; c++) {
        if (c + 1 < NCHUNK) {
            load_stage((c + 1) & 1, c + 1);
            CP_COMMIT();
            CP_WAIT(1);
        } else {
            CP_WAIT(0);
        }
        __syncthreads();

        const uint32_t st = sb + (c & 1) * GSTAGE;
        #pragma unroll
        for (int kk = 0; kk < 2; kk++) {
            uint32_t ah[4][4], al[4][4], bh[2][4], bl[2][4];
            int arow = warpM * 64 + (lane & 15);
            int au = kk * 2 + (lane >> 4);
            #pragma unroll
            for (int mt = 0; mt < 4; mt++) {
                uint32_t off = swz(arow + mt * 16, au);
                ldsm4(ah[mt], st + off);
                ldsm4(al[mt], st + GOFF_ALO + off);
            }
            int brow = warpN * 32 + rB;
            int bu = kk * 2 + uB;
            #pragma unroll
            for (int nt2 = 0; nt2 < 2; nt2++) {
                uint32_t off = swz(brow + nt2 * 16, bu);
                ldsm4(bh[nt2], st + GOFF_BHI + off);
                ldsm4(bl[nt2], st + GOFF_BLO + off);
            }
            #pragma unroll
            for (int mt = 0; mt < 4; mt++)
                #pragma unroll
                for (int nt = 0; nt < 4; nt++) {
                    const uint32_t* pbh = &bh[nt >> 1][(nt & 1) * 2];
                    const uint32_t* pbl = &bl[nt >> 1][(nt & 1) * 2];
                    mma16816(acc[mt][nt], ah[mt], pbh);
                    mma16816(acc[mt][nt], ah[mt], pbl);
                    mma16816(acc[mt][nt], al[mt], pbh);
                }
        }
        __syncthreads();
    }

    // ---- epilogue ----
    const float scl = (mode == 0 && z == 0) ? QSCALE : 1.f;
    __nv_bfloat16 *hiA = nullptr, *loA = nullptr;
    if (mode == 0) {
        if (z == 0) { hiA = g_qhi; loA = g_qlo; }
        else if (z == 1) { hiA = g_khi; loA = g_klo; }
        else { hiA = g_vhi; loA = g_vlo; }
    }

    #pragma unroll
    for (int mt = 0; mt < 4; mt++) {
        #pragma unroll
        for (int nt = 0; nt < 4; nt++) {
            int colb = nBase + warpN * 32 + nt * 8 + (lane & 3) * 2;
            #pragma unroll
            for (int h2 = 0; h2 < 2; h2++) {
                int row = mBase + warpM * 64 + mt * 16 + (lane >> 2) + h2 * 8;
                int b = row >> 11;
                int s = row & 2047;
                #pragma unroll
                for (int e = 0; e < 2; e++) {
                    int n = colb + e;
                    float v = acc[mt][nt][h2 * 2 + e] + bias[n];
                    if (mode == 0) {
                        v *= scl;
                        int h = n & 15, dk = n >> 4;
                        size_t adr = ((size_t)(b * HH + h) * SS + s) * DK + dk;
                        __nv_bfloat16 hv = __float2bfloat16(v);
                        hiA[adr] = hv;
                        loA[adr] = __float2bfloat16(v - __bfloat162float(hv));
                    } else {
                        outp[(size_t)row * DD + n] = v;
                    }
                }
            }
        }
    }
}

// ---------------------------------------------------------------------------
// HMMA flash attention, causal. CTA: 64 q-rows, 4 warps (16 rows each).
// ---------------------------------------------------------------------------
#define AT_KHI 0
#define AT_KLO 8192
#define AT_VHI 16384
#define AT_VLO 24576

__global__ __launch_bounds__(128) void fattn_kernel()
{
    __shared__ char smem[32768];
    const uint32_t sb = smem_u32(smem);

    const int tid  = threadIdx.x;
    const int wid  = tid >> 5;
    const int lane = tid & 31;
    const int g    = lane >> 2;
    const int tq   = lane & 3;
    const int bh   = blockIdx.y;
    const int qt   = gridDim.x - 1 - blockIdx.x;

    const size_t hb = (size_t)bh * SS * DK;
    const __nv_bfloat16* Qhi = g_qhi + hb;
    const __nv_bfloat16* Qlo = g_qlo + hb;
    const __nv_bfloat16* Khi = g_khi + hb;
    const __nv_bfloat16* Klo = g_klo + hb;
    const __nv_bfloat16* Vhi = g_vhi + hb;
    const __nv_bfloat16* Vlo = g_vlo + hb;

    #pragma unroll
    for (int p = 0; p < 4; p++) {
        int idx = tid + p * 128;
        int row = idx >> 3, u = idx & 7;
        size_t go = (size_t)(qt * 64 + row) * DK + u * 8;
        uint32_t s = swzV(row, u);
        cp16(sb + AT_KHI + s, Qhi + go);
        cp16(sb + AT_KLO + s, Qlo + go);
    }
    CP_COMMIT(); CP_WAIT(0);
    __syncthreads();

    uint32_t qh[4][4], ql[4][4];
    {
        int arow = wid * 16 + (lane & 15);
        int au = lane >> 4;
        #pragma unroll
        for (int ch = 0; ch < 4; ch++) {
            uint32_t off = swzV(arow, ch * 2 + au);
            ldsm4(qh[ch], sb + AT_KHI + off);
            ldsm4(ql[ch], sb + AT_KLO + off);
        }
    }
    __syncthreads();

    float o[8][4];
    #pragma unroll
    for (int m = 0; m < 8; m++)
        #pragma unroll
        for (int e = 0; e < 4; e++) o[m][e] = 0.f;
    float m1 = -1e30f, m2 = -1e30f, l1 = 0.f, l2 = 0.f;

    const int rB = ((lane >> 4) << 3) + (lane & 7);
    const int uB = (lane >> 3) & 1;
    const int rV = (((lane >> 3) & 1) << 3) + (lane & 7);
    const int uV = lane >> 4;

    for (int kt = 0; kt <= qt; kt++) {
        __syncthreads();
        #pragma unroll
        for (int p = 0; p < 4; p++) {
            int idx = tid + p * 128;
            int row = idx >> 3, u = idx & 7;
            size_t go = (size_t)(kt * 64 + row) * DK + u * 8;
            uint32_t s = swzV(row, u);
            cp16(sb + AT_KHI + s, Khi + go);
            cp16(sb + AT_KLO + s, Klo + go);
            cp16(sb + AT_VHI + s, Vhi + go);
            cp16(sb + AT_VLO + s, Vlo + go);
        }
        CP_COMMIT(); CP_WAIT(0);
        __syncthreads();

        float s[8][4];
        #pragma unroll
        for (int m = 0; m < 8; m++)
            #pragma unroll
            for (int e = 0; e < 4; e++) s[m][e] = 0.f;

        #pragma unroll
        for (int ch = 0; ch < 4; ch++) {
            uint32_t kh[4][4], kl[4][4];
            #pragma unroll
            for (int p = 0; p < 4; p++) {
                uint32_t off = swzV(p * 16 + rB, ch * 2 + uB);
                ldsm4(kh[p], sb + AT_KHI + off);
                ldsm4(kl[p], sb + AT_KLO + off);
            }
            #pragma unroll
            for (int p = 0; p < 4; p++) {
                mma16816(s[2*p],   qh[ch], &kh[p][0]);
                mma16816(s[2*p],   qh[ch], &kl[p][0]);
                mma16816(s[2*p],   ql[ch], &kh[p][0]);
                mma16816(s[2*p+1], qh[ch], &kh[p][2]);
                mma16816(s[2*p+1], qh[ch], &kl[p][2]);
                mma16816(s[2*p+1], ql[ch], &kh[p][2]);
            }
        }

        if (kt == qt) {
            int rowA = wid * 16 + g;
            int rowBr = rowA + 8;
            #pragma unroll
            for (int m = 0; m < 8; m++) {
                int c0 = m * 8 + tq * 2;
                if (c0     > rowA)  s[m][0] = -1e30f;
                if (c0 + 1 > rowA)  s[m][1] = -1e30f;
                if (c0     > rowBr) s[m][2] = -1e30f;
                if (c0 + 1 > rowBr) s[m][3] = -1e30f;
            }
        }

        float mx1 = -1e30f, mx2 = -1e30f;
        #pragma unroll
        for (int m = 0; m < 8; m++) {
            mx1 = fmaxf(mx1, fmaxf(s[m][0], s[m][1]));
            mx2 = fmaxf(mx2, fmaxf(s[m][2], s[m][3]));
        }
        mx1 = fmaxf(mx1, __shfl_xor_sync(0xffffffffu, mx1, 1));
        mx1 = fmaxf(mx1, __shfl_xor_sync(0xffffffffu, mx1, 2));
        mx2 = fmaxf(mx2, __shfl_xor_sync(0xffffffffu, mx2, 1));
        mx2 = fmaxf(mx2, __shfl_xor_sync(0xffffffffu, mx2, 2));
        float nm1 = fmaxf(m1, mx1), nm2 = fmaxf(m2, mx2);
        float a1 = fexp2(m1 - nm1), a2 = fexp2(m2 - nm2);
        float r1 = 0.f, r2 = 0.f;
        #pragma unroll
        for (int m = 0; m < 8; m++) {
            s[m][0] = fexp2(s[m][0] - nm1);
            s[m][1] = fexp2(s[m][1] - nm1);
            s[m][2] = fexp2(s[m][2] - nm2);
            s[m][3] = fexp2(s[m][3] - nm2);
            r1 += s[m][0] + s[m][1];
            r2 += s[m][2] + s[m][3];
        }
        r1 += __shfl_xor_sync(0xffffffffu, r1, 1);
        r1 += __shfl_xor_sync(0xffffffffu, r1, 2);
        r2 += __shfl_xor_sync(0xffffffffu, r2, 1);
        r2 += __shfl_xor_sync(0xffffffffu, r2, 2);
        l1 = l1 * a1 + r1;
        l2 = l2 * a2 + r2;
        m1 = nm1; m2 = nm2;
        #pragma unroll
        for (int m = 0; m < 8; m++) {
            o[m][0] *= a1; o[m][1] *= a1;
            o[m][2] *= a2; o[m][3] *= a2;
        }

        uint32_t ph[4][4], pl[4][4];
        #pragma unroll
        for (int jc = 0; jc < 4; jc++) {
            float d0, d1;
            ph[jc][0] = packbf2_res(s[2*jc][0],   s[2*jc][1],   d0, d1);
            pl[jc][0] = packbf2(d0, d1);
            ph[jc][1] = packbf2_res(s[2*jc][2],   s[2*jc][3],   d0, d1);
            pl[jc][1] = packbf2(d0, d1);
            ph[jc][2] = packbf2_res(s[2*jc+1][0], s[2*jc+1][1], d0, d1);
            pl[jc][2] = packbf2(d0, d1);
            ph[jc][3] = packbf2_res(s[2*jc+1][2], s[2*jc+1][3], d0, d1);
            pl[jc][3] = packbf2(d0, d1);
        }

        #pragma unroll
        for (int jc = 0; jc < 4; jc++) {
            uint32_t vh[4][4], vl[4][4];
            #pragma unroll
            for (int dp = 0; dp < 4; dp++) {
                uint32_t off = swzV(jc * 16 + rV, 2 * dp + uV);
                ldsm4t(vh[dp], sb + AT_VHI + off);
                ldsm4t(vl[dp], sb + AT_VLO + off);
            }
            #pragma unroll
            for (int dp = 0; dp < 4; dp++) {
                mma16816(o[2*dp],   ph[jc], &vh[dp][0]);
                mma16816(o[2*dp],   ph[jc], &vl[dp][0]);
                mma16816(o[2*dp],   pl[jc], &vh[dp][0]);
                mma16816(o[2*dp+1], ph[jc], &vh[dp][2]);
                mma16816(o[2*dp+1], ph[jc], &vl[dp][2]);
                mma16816(o[2*dp+1], pl[jc], &vh[dp][2]);
            }
        }
    }

    const float inv1 = 1.f / l1, inv2 = 1.f / l2;
    const int b = bh >> 4;
    const int h = bh & 15;
    const int sg1 = qt * 64 + wid * 16 + g;
    const int sg2 = sg1 + 8;
    #pragma unroll
    for (int m = 0; m < 8; m++) {
        int col = h * 64 + m * 8 + tq * 2;
        size_t a1i = ((size_t)(b * SS + sg1) * DD + col) >> 1;
        size_t a2i = ((size_t)(b * SS + sg2) * DD + col) >> 1;
        float f0 = o[m][0] * inv1, f1 = o[m][1] * inv1;
        float f2 = o[m][2] * inv2, f3 = o[m][3] * inv2;
        float d0, d1;
        uint32_t hi1 = packbf2_res(f0, f1, d0, d1);
        uint32_t lo1 = packbf2(d0, d1);
        uint32_t hi2 = packbf2_res(f2, f3, d0, d1);
        uint32_t lo2 = packbf2(d0, d1);
        ((uint32_t*)g_chi)[a1i] = hi1;
        ((uint32_t*)g_clo)[a1i] = lo1;
        ((uint32_t*)g_chi)[a2i] = hi2;
        ((uint32_t*)g_clo)[a2i] = lo2;
    }
}

// ---------------------------------------------------------------------------
extern "C" void kernel_launch(void* const* d_in, const int* in_sizes, int n_in,
                              void* d_out, int out_size)
{
    const float* q   = (const float*)d_in[0];
    const float* k   = (const float*)d_in[1];
    const float* v   = (const float*)d_in[2];
    // d_in[3] = mask (causal tril; handled in-kernel)
    const float* w_q = (const float*)d_in[4];
    const float* b_q = (const float*)d_in[5];
    const float* w_k = (const float*)d_in[6];
    const float* b_k = (const float*)d_in[7];
    const float* w_v = (const float*)d_in[8];
    const float* b_v = (const float*)d_in[9];
    const float* w_o = (const float*)d_in[10];
    const float* b_o = (const float*)d_in[11];
    float* out = (float*)d_out;

    // 0) fused split fp32 -> bf16 hi/lo (1 launch)
    split_all_kernel<<<28672, 256>>>(q, k, v, w_q, w_k, w_v, w_o);

    // 1) QKV projections on HMMA (bf16x3), fused grid.z = 3
    const int gsm = 2 * GSTAGE;   // 64KB
    cudaFuncSetAttribute(hmma_gemm_kernel,
                         cudaFuncAttributeMaxDynamicSharedMemorySize, gsm);
    hmma_gemm_kernel<<<dim3(DD / BN, MTOT / BM, 3), 256, gsm>>>(
        0, b_q, b_k, b_v, nullptr);

    // 2) causal flash attention on HMMA
    fattn_kernel<<<dim3(SS / 64, BB * HH), 128>>>();

    // 3) output projection on HMMA
    hmma_gemm_kernel<<<dim3(DD / BN, MTOT / BM, 1), 256, gsm>>>(
        1, b_o, nullptr, nullptr, out);
}

// round 6
// speedup vs baseline: 2.4423x; 1.0370x over previous
#include <cuda_runtime.h>
#include <cuda_bf16.h>
#include <math.h>
#include <stdint.h>

// Problem dims
#define BB 4
#define SS 2048
#define DD 1024
#define HH 16
#define DK 64
#define MTOT (BB*SS)          // 8192

constexpr size_t MKc = (size_t)MTOT * DD;   // 8388608
constexpr size_t KNc = (size_t)DD * DD;     // 1048576
constexpr size_t HSZ = (size_t)BB * HH * SS * DK;  // 8388608

// 0.125 * log2(e): folds attention scale + exp->exp2 conversion into Q
#define QSCALE 0.18033688011112042f

// ---------------- scratch (__device__ globals; no allocs allowed) ----------
__device__ __nv_bfloat16 g_ahi[3*MKc];       // q,k,v inputs (GEMM A)
__device__ __nv_bfloat16 g_alo[3*MKc];
__device__ __nv_bfloat16 g_whi[4*KNc];       // wq,wk,wv,wo
__device__ __nv_bfloat16 g_wlo[4*KNc];
__device__ __nv_bfloat16 g_chi[MKc];         // context hi/lo (oproj A)
__device__ __nv_bfloat16 g_clo[MKc];
// projected q/k/v hi/lo in [b,h,s,dk]; q pre-scaled by QSCALE
__device__ __nv_bfloat16 g_qhi[HSZ], g_qlo[HSZ];
__device__ __nv_bfloat16 g_khi[HSZ], g_klo[HSZ];
__device__ __nv_bfloat16 g_vhi[HSZ], g_vlo[HSZ];

// ---------------- PTX helpers ---------------------------------------------
__device__ __forceinline__ uint32_t smem_u32(const void* p) {
    uint32_t a;
    asm("{ .reg .u64 t; cvta.to.shared.u64 t, %1; cvt.u32.u64 %0, t; }"
        : "=r"(a) : "l"(p));
    return a;
}

__device__ __forceinline__ void cp16(uint32_t s, const void* g) {
    asm volatile("cp.async.cg.shared.global [%0], [%1], 16;" :: "r"(s), "l"(g));
}
#define CP_COMMIT() asm volatile("cp.async.commit_group;" ::: "memory")
#define CP_WAIT(n)  asm volatile("cp.async.wait_group %0;" :: "n"(n) : "memory")

__device__ __forceinline__ void ldsm4(uint32_t* r, uint32_t addr) {
    asm volatile("ldmatrix.sync.aligned.m8n8.x4.shared.b16 {%0,%1,%2,%3}, [%4];"
                 : "=r"(r[0]), "=r"(r[1]), "=r"(r[2]), "=r"(r[3]) : "r"(addr));
}
__device__ __forceinline__ void ldsm4t(uint32_t* r, uint32_t addr) {
    asm volatile("ldmatrix.sync.aligned.m8n8.x4.trans.shared.b16 {%0,%1,%2,%3}, [%4];"
                 : "=r"(r[0]), "=r"(r[1]), "=r"(r[2]), "=r"(r[3]) : "r"(addr));
}
__device__ __forceinline__ void mma16816(float* c, const uint32_t* a, const uint32_t* b) {
    asm volatile("mma.sync.aligned.m16n8k16.row.col.f32.bf16.bf16.f32 "
                 "{%0,%1,%2,%3}, {%4,%5,%6,%7}, {%8,%9}, {%0,%1,%2,%3};"
                 : "+f"(c[0]), "+f"(c[1]), "+f"(c[2]), "+f"(c[3])
                 : "r"(a[0]), "r"(a[1]), "r"(a[2]), "r"(a[3]),
                   "r"(b[0]), "r"(b[1]));
}

// GEMM smem swizzle: 64B rows (4x16B units)
__device__ __forceinline__ uint32_t swz(int row, int u) {
    return (uint32_t)(row * 64 + ((u ^ ((row >> 1) & 3)) << 4));
}
// Attention smem swizzle: 128B rows (8x16B units)
__device__ __forceinline__ uint32_t swzV(int row, int u) {
    return (uint32_t)(row * 128 + ((u ^ (row & 7)) << 4));
}

// fast 2^t on FMA/ALU pipes (no MUFU). t <= ~0; clamped at -126.
__device__ __forceinline__ float fexp2(float t) {
    t = fmaxf(t, -126.f);
    float tt = t + 12582912.f;
    float fi = tt - 12582912.f;
    float f  = t - fi;
    int   ei = __float_as_int(tt) - 0x4B400000;
    float sc = __int_as_float((ei + 127) << 23);
    float p = fmaf(f, 1.33335581e-3f, 9.61812911e-3f);
    p = fmaf(f, p, 5.55041087e-2f);
    p = fmaf(f, p, 2.40226507e-1f);
    p = fmaf(f, p, 6.93147181e-1f);
    p = fmaf(f, p, 1.0f);
    return sc * p;
}

__device__ __forceinline__ uint32_t packbf2(float f0, float f1) {
    __nv_bfloat162 h = __floats2bfloat162_rn(f0, f1);
    return *(uint32_t*)&h;
}
__device__ __forceinline__ uint32_t packbf2_res(float f0, float f1, float& r0, float& r1) {
    __nv_bfloat162 h = __floats2bfloat162_rn(f0, f1);
    r0 = f0 - __bfloat162float(__low2bfloat16(h));
    r1 = f1 - __bfloat162float(__high2bfloat16(h));
    return *(uint32_t*)&h;
}

// ---------------------------------------------------------------------------
// fused split: all 3 inputs + 4 weights in ONE launch. fp32 -> bf16 hi + lo.
// ---------------------------------------------------------------------------
__global__ __launch_bounds__(256) void split_all_kernel(
    const float* __restrict__ q, const float* __restrict__ k, const float* __restrict__ v,
    const float* __restrict__ wq, const float* __restrict__ wk,
    const float* __restrict__ wv, const float* __restrict__ wo)
{
    const int bid = blockIdx.x;
    const float* src;
    __nv_bfloat16 *hi, *lo;
    int i;
    if (bid < 24576) {
        int r = bid >> 13;
        src = (r == 0) ? q : (r == 1) ? k : v;
        hi = g_ahi + (size_t)r * MKc;
        lo = g_alo + (size_t)r * MKc;
        i = ((bid & 8191) << 8) + threadIdx.x;
    } else {
        int t = bid - 24576;
        int r = t >> 10;
        src = (r == 0) ? wq : (r == 1) ? wk : (r == 2) ? wv : wo;
        hi = g_whi + (size_t)r * KNc;
        lo = g_wlo + (size_t)r * KNc;
        i = ((t & 1023) << 8) + threadIdx.x;
    }
    float4 x = ((const float4*)src)[i];
    float v0 = x.x, v1 = x.y, v2 = x.z, v3 = x.w;
    __nv_bfloat16 h0 = __float2bfloat16(v0), h1 = __float2bfloat16(v1);
    __nv_bfloat16 h2 = __float2bfloat16(v2), h3 = __float2bfloat16(v3);
    __nv_bfloat16 l0 = __float2bfloat16(v0 - __bfloat162float(h0));
    __nv_bfloat16 l1 = __float2bfloat16(v1 - __bfloat162float(h1));
    __nv_bfloat16 l2 = __float2bfloat16(v2 - __bfloat162float(h2));
    __nv_bfloat16 l3 = __float2bfloat16(v3 - __bfloat162float(h3));
    ((__nv_bfloat162*)hi)[2*i + 0] = __halves2bfloat162(h0, h1);
    ((__nv_bfloat162*)hi)[2*i + 1] = __halves2bfloat162(h2, h3);
    ((__nv_bfloat162*)lo)[2*i + 0] = __halves2bfloat162(l0, l1);
    ((__nv_bfloat162*)lo)[2*i + 1] = __halves2bfloat162(l2, l3);
}

// ---------------------------------------------------------------------------
// HMMA bf16x3 GEMM: Y = A(Mx1024) @ W(Nx1024)^T + bias
// CTA tile 128x128, BK=32, 8 warps as 2(M)x4(N), warp tile 64x32.
// 3-stage cp.async pipeline (96KB dynamic smem), one barrier per chunk.
// ---------------------------------------------------------------------------
#define BM 128
#define BN 128
#define BK 32
#define NCHUNK (DD / BK)     // 32
#define GOFF_ALO 8192
#define GOFF_BHI 16384
#define GOFF_BLO 24576
#define GSTAGE   32768
#define GNSTG    3

__global__ __launch_bounds__(256, 1)
void hmma_gemm_kernel(int mode, const float* __restrict__ bq,
                      const float* __restrict__ bk, const float* __restrict__ bv,
                      float* __restrict__ outp)
{
    extern __shared__ char smem[];

    const int tid = threadIdx.x;
    const int wid = tid >> 5;
    const int lane = tid & 31;
    const int warpM = wid & 1;
    const int warpN = wid >> 1;
    const int mBase = blockIdx.y * BM;
    const int nBase = blockIdx.x * BN;
    const int z = blockIdx.z;

    const __nv_bfloat16 *Ahi, *Alo, *Bhi, *Blo;
    const float* bias;
    if (mode == 0) {
        Ahi = g_ahi + (size_t)z * MKc; Alo = g_alo + (size_t)z * MKc;
        Bhi = g_whi + (size_t)z * KNc; Blo = g_wlo + (size_t)z * KNc;
        bias = (z == 0) ? bq : (z == 1) ? bk : bv;
    } else {
        Ahi = g_chi; Alo = g_clo;
        Bhi = g_whi + 3 * KNc; Blo = g_wlo + 3 * KNc;
        bias = bq;
    }

    const uint32_t sb = smem_u32(smem);

    float acc[4][4][4];
    #pragma unroll
    for (int mt = 0; mt < 4; mt++)
        #pragma unroll
        for (int nt = 0; nt < 4; nt++)
            #pragma unroll
            for (int e = 0; e < 4; e++) acc[mt][nt][e] = 0.f;

    auto load_stage = [&](int stage, int chunk) {
        const int k0 = chunk * BK;
        const uint32_t st = sb + stage * GSTAGE;
        #pragma unroll
        for (int p = 0; p < 8; p++) {
            int g = tid + p * 256;
            int part = (g >> 9) & 1;
            int idx = g & 511;
            int row = idx >> 2, u = idx & 3;
            if (g < 1024) {
                const __nv_bfloat16* src = part ? Alo : Ahi;
                cp16(st + part * 8192 + swz(row, u),
                     src + (size_t)(mBase + row) * DD + k0 + u * 8);
            } else {
                const __nv_bfloat16* src = part ? Blo : Bhi;
                cp16(st + GOFF_BHI + part * 8192 + swz(row, u),
                     src + (size_t)(nBase + row) * DD + k0 + u * 8);
            }
        }
    };

    load_stage(0, 0); CP_COMMIT();
    load_stage(1, 1); CP_COMMIT();

    const int rB = ((lane >> 4) << 3) + (lane & 7);
    const int uB = (lane >> 3) & 1;

    int stage = 0;
    for (int c = 0; c < NCHUNK; c++) {
        CP_WAIT(1);
        __syncthreads();

        const uint32_t st = sb + stage * GSTAGE;
        #pragma unroll
        for (int kk = 0; kk < 2; kk++) {
            uint32_t ah[4][4], al[4][4], bh[2][4], bl[2][4];
            int arow = warpM * 64 + (lane & 15);
            int au = kk * 2 + (lane >> 4);
            #pragma unroll
            for (int mt = 0; mt < 4; mt++) {
                uint32_t off = swz(arow + mt * 16, au);
                ldsm4(ah[mt], st + off);
                ldsm4(al[mt], st + GOFF_ALO + off);
            }
            int brow = warpN * 32 + rB;
            int bu = kk * 2 + uB;
            #pragma unroll
            for (int nt2 = 0; nt2 < 2; nt2++) {
                uint32_t off = swz(brow + nt2 * 16, bu);
                ldsm4(bh[nt2], st + GOFF_BHI + off);
                ldsm4(bl[nt2], st + GOFF_BLO + off);
            }
            #pragma unroll
            for (int mt = 0; mt < 4; mt++)
                #pragma unroll
                for (int nt = 0; nt < 4; nt++) {
                    const uint32_t* pbh = &bh[nt >> 1][(nt & 1) * 2];
                    const uint32_t* pbl = &bl[nt >> 1][(nt & 1) * 2];
                    mma16816(acc[mt][nt], ah[mt], pbh);
                    mma16816(acc[mt][nt], ah[mt], pbl);
                    mma16816(acc[mt][nt], al[mt], pbh);
                }
        }

        // prefetch chunk c+2 into the stage freed at barrier above
        if (c + 2 < NCHUNK) {
            int ns = stage + 2; if (ns >= GNSTG) ns -= GNSTG;
            load_stage(ns, c + 2);
        }
        CP_COMMIT();
        stage = (stage + 1 == GNSTG) ? 0 : stage + 1;
    }

    // ---- epilogue ----
    const float scl = (mode == 0 && z == 0) ? QSCALE : 1.f;
    __nv_bfloat16 *hiA = nullptr, *loA = nullptr;
    if (mode == 0) {
        if (z == 0) { hiA = g_qhi; loA = g_qlo; }
        else if (z == 1) { hiA = g_khi; loA = g_klo; }
        else { hiA = g_vhi; loA = g_vlo; }
    }

    #pragma unroll
    for (int mt = 0; mt < 4; mt++) {
        #pragma unroll
        for (int nt = 0; nt < 4; nt++) {
            int colb = nBase + warpN * 32 + nt * 8 + (lane & 3) * 2;
            #pragma unroll
            for (int h2 = 0; h2 < 2; h2++) {
                int row = mBase + warpM * 64 + mt * 16 + (lane >> 2) + h2 * 8;
                int b = row >> 11;
                int s = row & 2047;
                #pragma unroll
                for (int e = 0; e < 2; e++) {
                    int n = colb + e;
                    float v = acc[mt][nt][h2 * 2 + e] + bias[n];
                    if (mode == 0) {
                        v *= scl;
                        int h = n & 15, dk = n >> 4;
                        size_t adr = ((size_t)(b * HH + h) * SS + s) * DK + dk;
                        __nv_bfloat16 hv = __float2bfloat16(v);
                        hiA[adr] = hv;
                        loA[adr] = __float2bfloat16(v - __bfloat162float(hv));
                    } else {
                        outp[(size_t)row * DD + n] = v;
                    }
                }
            }
        }
    }
}

// ---------------------------------------------------------------------------
// HMMA flash attention, causal. CTA: 64 q-rows, 4 warps.
// 3-stage cp.async K/V pipeline (96KB dynamic smem), one barrier per kt.
// ---------------------------------------------------------------------------
#define AT_KLO 8192
#define AT_VHI 16384
#define AT_VLO 24576
#define ASTAGE 32768
#define ANSTG  3

__global__ __launch_bounds__(128) void fattn_kernel()
{
    extern __shared__ char smem[];
    const uint32_t sb = smem_u32(smem);

    const int tid  = threadIdx.x;
    const int wid  = tid >> 5;
    const int lane = tid & 31;
    const int g    = lane >> 2;
    const int tq   = lane & 3;
    const int bh   = blockIdx.y;
    const int qt   = gridDim.x - 1 - blockIdx.x;

    const size_t hb = (size_t)bh * SS * DK;
    const __nv_bfloat16* Qhi = g_qhi + hb;
    const __nv_bfloat16* Qlo = g_qlo + hb;
    const __nv_bfloat16* Khi = g_khi + hb;
    const __nv_bfloat16* Klo = g_klo + hb;
    const __nv_bfloat16* Vhi = g_vhi + hb;
    const __nv_bfloat16* Vlo = g_vlo + hb;

    // ---- stage Q tile into stage-0 K slots, pull frags to regs ----
    #pragma unroll
    for (int p = 0; p < 4; p++) {
        int idx = tid + p * 128;
        int row = idx >> 3, u = idx & 7;
        size_t go = (size_t)(qt * 64 + row) * DK + u * 8;
        uint32_t s = swzV(row, u);
        cp16(sb + s, Qhi + go);
        cp16(sb + AT_KLO + s, Qlo + go);
    }
    CP_COMMIT(); CP_WAIT(0);
    __syncthreads();

    uint32_t qh[4][4], ql[4][4];
    {
        int arow = wid * 16 + (lane & 15);
        int au = lane >> 4;
        #pragma unroll
        for (int ch = 0; ch < 4; ch++) {
            uint32_t off = swzV(arow, ch * 2 + au);
            ldsm4(qh[ch], sb + off);
            ldsm4(ql[ch], sb + AT_KLO + off);
        }
    }
    __syncthreads();   // all warps have Q frags; stage 0 free for K/V

    auto load_kv = [&](int stage, int kt) {
        const uint32_t st = sb + stage * ASTAGE;
        #pragma unroll
        for (int p = 0; p < 4; p++) {
            int idx = tid + p * 128;
            int row = idx >> 3, u = idx & 7;
            size_t go = (size_t)(kt * 64 + row) * DK + u * 8;
            uint32_t s = swzV(row, u);
            cp16(st + s, Khi + go);
            cp16(st + AT_KLO + s, Klo + go);
            cp16(st + AT_VHI + s, Vhi + go);
            cp16(st + AT_VLO + s, Vlo + go);
        }
    };

    load_kv(0, 0); CP_COMMIT();
    if (qt >= 1) load_kv(1, 1);
    CP_COMMIT();

    float o[8][4];
    #pragma unroll
    for (int m = 0; m < 8; m++)
        #pragma unroll
        for (int e = 0; e < 4; e++) o[m][e] = 0.f;
    float m1 = -1e30f, m2 = -1e30f, l1 = 0.f, l2 = 0.f;

    const int rB = ((lane >> 4) << 3) + (lane & 7);
    const int uB = (lane >> 3) & 1;
    const int rV = (((lane >> 3) & 1) << 3) + (lane & 7);
    const int uV = lane >> 4;

    int stage = 0;
    for (int kt = 0; kt <= qt; kt++) {
        CP_WAIT(1);
        __syncthreads();
        const uint32_t st = sb + stage * ASTAGE;

        // ---- S = Q @ K^T (3-pass hi/lo) ----
        float s[8][4];
        #pragma unroll
        for (int m = 0; m < 8; m++)
            #pragma unroll
            for (int e = 0; e < 4; e++) s[m][e] = 0.f;

        #pragma unroll
        for (int ch = 0; ch < 4; ch++) {
            uint32_t kh[4][4], kl[4][4];
            #pragma unroll
            for (int p = 0; p < 4; p++) {
                uint32_t off = swzV(p * 16 + rB, ch * 2 + uB);
                ldsm4(kh[p], st + off);
                ldsm4(kl[p], st + AT_KLO + off);
            }
            #pragma unroll
            for (int p = 0; p < 4; p++) {
                mma16816(s[2*p],   qh[ch], &kh[p][0]);
                mma16816(s[2*p],   qh[ch], &kl[p][0]);
                mma16816(s[2*p],   ql[ch], &kh[p][0]);
                mma16816(s[2*p+1], qh[ch], &kh[p][2]);
                mma16816(s[2*p+1], qh[ch], &kl[p][2]);
                mma16816(s[2*p+1], ql[ch], &kh[p][2]);
            }
        }

        if (kt == qt) {
            int rowA = wid * 16 + g;
            int rowBr = rowA + 8;
            #pragma unroll
            for (int m = 0; m < 8; m++) {
                int c0 = m * 8 + tq * 2;
                if (c0     > rowA)  s[m][0] = -1e30f;
                if (c0 + 1 > rowA)  s[m][1] = -1e30f;
                if (c0     > rowBr) s[m][2] = -1e30f;
                if (c0 + 1 > rowBr) s[m][3] = -1e30f;
            }
        }

        float mx1 = -1e30f, mx2 = -1e30f;
        #pragma unroll
        for (int m = 0; m < 8; m++) {
            mx1 = fmaxf(mx1, fmaxf(s[m][0], s[m][1]));
            mx2 = fmaxf(mx2, fmaxf(s[m][2], s[m][3]));
        }
        mx1 = fmaxf(mx1, __shfl_xor_sync(0xffffffffu, mx1, 1));
        mx1 = fmaxf(mx1, __shfl_xor_sync(0xffffffffu, mx1, 2));
        mx2 = fmaxf(mx2, __shfl_xor_sync(0xffffffffu, mx2, 1));
        mx2 = fmaxf(mx2, __shfl_xor_sync(0xffffffffu, mx2, 2));
        float nm1 = fmaxf(m1, mx1), nm2 = fmaxf(m2, mx2);
        float a1 = fexp2(m1 - nm1), a2 = fexp2(m2 - nm2);
        float r1 = 0.f, r2 = 0.f;
        #pragma unroll
        for (int m = 0; m < 8; m++) {
            s[m][0] = fexp2(s[m][0] - nm1);
            s[m][1] = fexp2(s[m][1] - nm1);
            s[m][2] = fexp2(s[m][2] - nm2);
            s[m][3] = fexp2(s[m][3] - nm2);
            r1 += s[m][0] + s[m][1];
            r2 += s[m][2] + s[m][3];
        }
        r1 += __shfl_xor_sync(0xffffffffu, r1, 1);
        r1 += __shfl_xor_sync(0xffffffffu, r1, 2);
        r2 += __shfl_xor_sync(0xffffffffu, r2, 1);
        r2 += __shfl_xor_sync(0xffffffffu, r2, 2);
        l1 = l1 * a1 + r1;
        l2 = l2 * a2 + r2;
        m1 = nm1; m2 = nm2;
        #pragma unroll
        for (int m = 0; m < 8; m++) {
            o[m][0] *= a1; o[m][1] *= a1;
            o[m][2] *= a2; o[m][3] *= a2;
        }

        uint32_t ph[4][4], pl[4][4];
        #pragma unroll
        for (int jc = 0; jc < 4; jc++) {
            float d0, d1;
            ph[jc][0] = packbf2_res(s[2*jc][0],   s[2*jc][1],   d0, d1);
            pl[jc][0] = packbf2(d0, d1);
            ph[jc][1] = packbf2_res(s[2*jc][2],   s[2*jc][3],   d0, d1);
            pl[jc][1] = packbf2(d0, d1);
            ph[jc][2] = packbf2_res(s[2*jc+1][0], s[2*jc+1][1], d0, d1);
            pl[jc][2] = packbf2(d0, d1);
            ph[jc][3] = packbf2_res(s[2*jc+1][2], s[2*jc+1][3], d0, d1);
            pl[jc][3] = packbf2(d0, d1);
        }

        #pragma unroll
        for (int jc = 0; jc < 4; jc++) {
            uint32_t vh[4][4], vl[4][4];
            #pragma unroll
            for (int dp = 0; dp < 4; dp++) {
                uint32_t off = swzV(jc * 16 + rV, 2 * dp + uV);
                ldsm4t(vh[dp], st + AT_VHI + off);
                ldsm4t(vl[dp], st + AT_VLO + off);
            }
            #pragma unroll
            for (int dp = 0; dp < 4; dp++) {
                mma16816(o[2*dp],   ph[jc], &vh[dp][0]);
                mma16816(o[2*dp],   ph[jc], &vl[dp][0]);
                mma16816(o[2*dp],   pl[jc], &vh[dp][0]);
                mma16816(o[2*dp+1], ph[jc], &vh[dp][2]);
                mma16816(o[2*dp+1], ph[jc], &vl[dp][2]);
                mma16816(o[2*dp+1], pl[jc], &vh[dp][2]);
            }
        }

        // prefetch kt+2 into the stage freed at this iteration's barrier
        if (kt + 2 <= qt) {
            int ns = stage + 2; if (ns >= ANSTG) ns -= ANSTG;
            load_kv(ns, kt + 2);
        }
        CP_COMMIT();
        stage = (stage + 1 == ANSTG) ? 0 : stage + 1;
    }

    const float inv1 = 1.f / l1, inv2 = 1.f / l2;
    const int b = bh >> 4;
    const int h = bh & 15;
    const int sg1 = qt * 64 + wid * 16 + g;
    const int sg2 = sg1 + 8;
    #pragma unroll
    for (int m = 0; m < 8; m++) {
        int col = h * 64 + m * 8 + tq * 2;
        size_t a1i = ((size_t)(b * SS + sg1) * DD + col) >> 1;
        size_t a2i = ((size_t)(b * SS + sg2) * DD + col) >> 1;
        float f0 = o[m][0] * inv1, f1 = o[m][1] * inv1;
        float f2 = o[m][2] * inv2, f3 = o[m][3] * inv2;
        float d0, d1;
        uint32_t hi1 = packbf2_res(f0, f1, d0, d1);
        uint32_t lo1 = packbf2(d0, d1);
        uint32_t hi2 = packbf2_res(f2, f3, d0, d1);
        uint32_t lo2 = packbf2(d0, d1);
        ((uint32_t*)g_chi)[a1i] = hi1;
        ((uint32_t*)g_clo)[a1i] = lo1;
        ((uint32_t*)g_chi)[a2i] = hi2;
        ((uint32_t*)g_clo)[a2i] = lo2;
    }
}

// ---------------------------------------------------------------------------
extern "C" void kernel_launch(void* const* d_in, const int* in_sizes, int n_in,
                              void* d_out, int out_size)
{
    const float* q   = (const float*)d_in[0];
    const float* k   = (const float*)d_in[1];
    const float* v   = (const float*)d_in[2];
    // d_in[3] = mask (causal tril; handled in-kernel)
    const float* w_q = (const float*)d_in[4];
    const float* b_q = (const float*)d_in[5];
    const float* w_k = (const float*)d_in[6];
    const float* b_k = (const float*)d_in[7];
    const float* w_v = (const float*)d_in[8];
    const float* b_v = (const float*)d_in[9];
    const float* w_o = (const float*)d_in[10];
    const float* b_o = (const float*)d_in[11];
    float* out = (float*)d_out;

    // 0) fused split fp32 -> bf16 hi/lo (1 launch)
    split_all_kernel<<<28672, 256>>>(q, k, v, w_q, w_k, w_v, w_o);

    // 1) QKV projections on HMMA (bf16x3), fused grid.z = 3
    const int gsm = GNSTG * GSTAGE;   // 96KB
    cudaFuncSetAttribute(hmma_gemm_kernel,
                         cudaFuncAttributeMaxDynamicSharedMemorySize, gsm);
    hmma_gemm_kernel<<<dim3(DD / BN, MTOT / BM, 3), 256, gsm>>>(
        0, b_q, b_k, b_v, nullptr);

    // 2) causal flash attention on HMMA (3-stage pipeline)
    const int asm_ = ANSTG * ASTAGE;  // 96KB
    cudaFuncSetAttribute(fattn_kernel,
                         cudaFuncAttributeMaxDynamicSharedMemorySize, asm_);
    fattn_kernel<<<dim3(SS / 64, BB * HH), 128, asm_>>>();

    // 3) output projection on HMMA
    hmma_gemm_kernel<<<dim3(DD / BN, MTOT / BM, 1), 256, gsm>>>(
        1, b_o, nullptr, nullptr, out);
}